// round 1
// baseline (speedup 1.0000x reference)
#include <cuda_runtime.h>
#include <math.h>

// Problem constants
#define Hh     8
#define Dd     64
#define INDIM  512
#define Bb     4
#define Nn     2048
#define INNER  512            // H*D
#define M_TOT  (Bb*Nn)        // 8192

// Scratch (allocation-free: __device__ globals)
__device__ float g_Qt[(size_t)Bb*INNER*Nn];    // [(b*512+o)][n]  (o = h*64+d)  -> [d-major][n] per head
__device__ float g_Kt[(size_t)Bb*INNER*Nn];    // same layout as Qt
__device__ float g_V [(size_t)Bb*Hh*Nn*Dd];    // [bh][n][d]
__device__ float g_A [(size_t)M_TOT*INNER];    // [m][o] attention output (rows of final GEMM)

// ---------------------------------------------------------------------------
// Generic NT GEMM: C[m,o] = sum_k X[m,k] * W[o,k]
// 64x64 tile, BK=32, 256 threads, 4x4 micro-tile. Transposed smem tiles
// (k-major) so compute loads are LDS.128 conflict-free.
// mode 0: epilogue -> g_Qt      (W = Wq,  N=512)
// mode 1: epilogue -> g_Kt/g_V  (W = Wkv, N=1024)
// mode 2: X = g_A, epilogue -> out + bias (W = Wo, N=512)
// ---------------------------------------------------------------------------
__global__ void __launch_bounds__(256) gemm_nt(
    const float* __restrict__ X, const float* __restrict__ W,
    const float* __restrict__ bias, float* __restrict__ out,
    int K, int mode)
{
    __shared__ float xt[32][68];   // [k][m], pad 68 (mult of 4 -> float4 aligned)
    __shared__ float wt[32][68];   // [k][o]

    const float* Xp = (mode == 2) ? g_A : X;

    const int tx = threadIdx.x & 15;
    const int ty = threadIdx.x >> 4;
    const int m0 = blockIdx.y * 64;
    const int n0 = blockIdx.x * 64;

    float acc[4][4] = {};

    for (int k0 = 0; k0 < K; k0 += 32) {
        // Load 64x32 tiles (coalesced on k), store transposed.
        #pragma unroll
        for (int e = threadIdx.x; e < 2048; e += 256) {
            int r = e >> 5, c = e & 31;
            xt[c][r] = Xp[(size_t)(m0 + r) * K + (k0 + c)];
            wt[c][r] = W [(size_t)(n0 + r) * K + (k0 + c)];
        }
        __syncthreads();

        #pragma unroll
        for (int kk = 0; kk < 32; kk++) {
            float4 a4 = *(const float4*)&xt[kk][ty * 4];
            float4 b4 = *(const float4*)&wt[kk][tx * 4];
            float av[4] = {a4.x, a4.y, a4.z, a4.w};
            float bv[4] = {b4.x, b4.y, b4.z, b4.w};
            #pragma unroll
            for (int i = 0; i < 4; i++)
                #pragma unroll
                for (int j = 0; j < 4; j++)
                    acc[i][j] += av[i] * bv[j];
        }
        __syncthreads();
    }

    // Epilogue
    #pragma unroll
    for (int i = 0; i < 4; i++) {
        int m = m0 + ty * 4 + i;
        int b = m >> 11;          // /2048
        int n = m & 2047;
        #pragma unroll
        for (int j = 0; j < 4; j++) {
            int o = n0 + tx * 4 + j;
            float v = acc[i][j];
            if (mode == 0) {
                g_Qt[(size_t)(b * INNER + o) * Nn + n] = v;
            } else if (mode == 1) {
                if (o < INNER) {
                    g_Kt[(size_t)(b * INNER + o) * Nn + n] = v;
                } else {
                    int oo = o - INNER;
                    g_V[(((size_t)(b * Hh + (oo >> 6)) * Nn + n) << 6) + (oo & 63)] = v;
                }
            } else {
                out[(size_t)m * INNER + o] = v + bias[o];
            }
        }
    }
}

// ---------------------------------------------------------------------------
// Flash attention, fp32. One block = one (b,h) x 64 query rows.
// S = (Q*scale) @ K^T via k-major smem tiles (outer-product, LDS.128),
// online softmax with shfl row-reductions (16-lane groups = one S row),
// P@V via row-major P (reuses the K buffer) and natural-layout V.
// ---------------------------------------------------------------------------
__global__ void __launch_bounds__(256) attn_kernel()
{
    __shared__ float qt[64][64];  // [d][q]   (scaled Q, transposed)
    __shared__ float kp[64][64];  // [d][key] during S; reused as P[row][key]
    __shared__ float vs[64][64];  // [key][d]

    const int tx = threadIdx.x & 15;
    const int ty = threadIdx.x >> 4;
    const int bh = blockIdx.y;          // b*8 + h
    const int q0 = blockIdx.x * 64;
    const float scale = 0.125f;         // 64^-0.5

    // Load Q tile (scaled). g_Qt row (bh*64+d) is n-contiguous -> coalesced.
    #pragma unroll
    for (int e = threadIdx.x; e < 4096; e += 256) {
        int d = e >> 6, nn = e & 63;
        qt[d][nn] = g_Qt[((size_t)bh * 64 + d) * Nn + q0 + nn] * scale;
    }

    float o_acc[4][4] = {};
    float m_run[4], l_run[4];
    #pragma unroll
    for (int i = 0; i < 4; i++) { m_run[i] = -1e30f; l_run[i] = 0.0f; }

    for (int t = 0; t < Nn; t += 64) {
        // Load K tile (transposed layout already) and V tile.
        #pragma unroll
        for (int e = threadIdx.x; e < 4096; e += 256) {
            int r = e >> 6, c = e & 63;
            kp[r][c] = g_Kt[((size_t)bh * 64 + r) * Nn + t + c];
            vs[r][c] = g_V [(((size_t)bh * Nn + t + r) << 6) + c];
        }
        __syncthreads();

        // S = Qs @ K^T  (4x4 per thread; rows = ty*4+i, keys = tx*4+j)
        float s[4][4] = {};
        #pragma unroll 8
        for (int kk = 0; kk < 64; kk++) {
            float4 a4 = *(const float4*)&qt[kk][ty * 4];
            float4 b4 = *(const float4*)&kp[kk][tx * 4];
            float av[4] = {a4.x, a4.y, a4.z, a4.w};
            float bv[4] = {b4.x, b4.y, b4.z, b4.w};
            #pragma unroll
            for (int i = 0; i < 4; i++)
                #pragma unroll
                for (int j = 0; j < 4; j++)
                    s[i][j] += av[i] * bv[j];
        }

        // Online softmax update. One S-row lives in 16 lanes (same ty group).
        float rm[4], corr[4], rs[4];
        #pragma unroll
        for (int i = 0; i < 4; i++) {
            rm[i] = fmaxf(fmaxf(s[i][0], s[i][1]), fmaxf(s[i][2], s[i][3]));
        }
        #pragma unroll
        for (int off = 1; off < 16; off <<= 1)
            #pragma unroll
            for (int i = 0; i < 4; i++)
                rm[i] = fmaxf(rm[i], __shfl_xor_sync(0xffffffffu, rm[i], off, 16));

        #pragma unroll
        for (int i = 0; i < 4; i++) {
            float mn = fmaxf(m_run[i], rm[i]);
            corr[i] = __expf(m_run[i] - mn);
            m_run[i] = mn;
            rs[i] = 0.0f;
            #pragma unroll
            for (int j = 0; j < 4; j++) {
                s[i][j] = __expf(s[i][j] - mn);
                rs[i] += s[i][j];
            }
        }
        #pragma unroll
        for (int off = 1; off < 16; off <<= 1)
            #pragma unroll
            for (int i = 0; i < 4; i++)
                rs[i] += __shfl_xor_sync(0xffffffffu, rs[i], off, 16);

        #pragma unroll
        for (int i = 0; i < 4; i++) {
            l_run[i] = l_run[i] * corr[i] + rs[i];
            #pragma unroll
            for (int j = 0; j < 4; j++)
                o_acc[i][j] *= corr[i];
        }

        __syncthreads();   // everyone done reading K from kp

        // Write P (row-major) into kp. float4 per (row,4 keys): conflict-free.
        #pragma unroll
        for (int i = 0; i < 4; i++)
            *(float4*)&kp[ty * 4 + i][tx * 4] =
                make_float4(s[i][0], s[i][1], s[i][2], s[i][3]);
        __syncthreads();

        // O += P @ V   (dims = tx*4+j)
        #pragma unroll 8
        for (int kk = 0; kk < 64; kk++) {
            float4 v4 = *(const float4*)&vs[kk][tx * 4];
            float vv[4] = {v4.x, v4.y, v4.z, v4.w};
            float pv[4];
            #pragma unroll
            for (int i = 0; i < 4; i++) pv[i] = kp[ty * 4 + i][kk];
            #pragma unroll
            for (int i = 0; i < 4; i++)
                #pragma unroll
                for (int j = 0; j < 4; j++)
                    o_acc[i][j] += pv[i] * vv[j];
        }
        __syncthreads();   // before next tile overwrites kp/vs
    }

    // Normalize and store to g_A[m][h*64+d]
    const int b = bh >> 3, h = bh & 7;
    #pragma unroll
    for (int i = 0; i < 4; i++) {
        float inv = 1.0f / l_run[i];
        size_t m = (size_t)b * Nn + q0 + ty * 4 + i;
        float4 r = make_float4(o_acc[i][0] * inv, o_acc[i][1] * inv,
                               o_acc[i][2] * inv, o_acc[i][3] * inv);
        *(float4*)&g_A[m * INNER + h * 64 + tx * 4] = r;
    }
}

// ---------------------------------------------------------------------------
extern "C" void kernel_launch(void* const* d_in, const int* in_sizes, int n_in,
                              void* d_out, int out_size)
{
    const float* x   = (const float*)d_in[0];
    const float* Wq  = (const float*)d_in[1];
    const float* Wkv = (const float*)d_in[2];
    const float* Wo  = (const float*)d_in[3];
    const float* bo  = (const float*)d_in[4];
    float* out = (float*)d_out;

    dim3 thr(256);

    // Q projection: N=512
    gemm_nt<<<dim3(INNER / 64, M_TOT / 64), thr>>>(x, Wq, nullptr, nullptr, INDIM, 0);
    // KV projection: N=1024
    gemm_nt<<<dim3(2 * INNER / 64, M_TOT / 64), thr>>>(x, Wkv, nullptr, nullptr, INDIM, 1);
    // Attention: 32 q-tiles x 32 (b,h)
    attn_kernel<<<dim3(Nn / 64, Bb * Hh), thr>>>();
    // Output projection + bias: N=512
    gemm_nt<<<dim3(INDIM / 64, M_TOT / 64), thr>>>(nullptr, Wo, bo, out, INNER, 2);
}

// round 2
// speedup vs baseline: 2.7829x; 2.7829x over previous
#include <cuda_runtime.h>
#include <math.h>

// Problem constants
#define Hh     8
#define Dd     64
#define INDIM  512
#define Bb     4
#define Nn     2048
#define INNER  512            // H*D
#define M_TOT  (Bb*Nn)        // 8192

// Scratch (allocation-free: __device__ globals)
__device__ float g_Q[(size_t)Bb*Hh*Nn*Dd];   // [bh][n][d], pre-scaled by 0.125
__device__ float g_K[(size_t)Bb*Hh*Nn*Dd];   // [bh][n][d]
__device__ float g_V[(size_t)Bb*Hh*Dd*Nn];   // [bh][d][n]  (transposed)
__device__ float g_A[(size_t)M_TOT*INNER];   // [m][o] attention output

// ---------------------------------------------------------------------------
// TF32 helpers
// ---------------------------------------------------------------------------
__device__ __forceinline__ unsigned f2tf(float f) {
    unsigned u;
    asm("cvt.rna.tf32.f32 %0, %1;" : "=r"(u) : "f"(f));
    return u;
}

// D = A*B + D,  m16n8k8, A row-major, B col-major, tf32 in, fp32 acc
__device__ __forceinline__ void mma8(float c[4], const unsigned a[4], const unsigned b[2]) {
    asm volatile(
        "mma.sync.aligned.m16n8k8.row.col.f32.tf32.tf32.f32 "
        "{%0,%1,%2,%3},{%4,%5,%6,%7},{%8,%9},{%0,%1,%2,%3};"
        : "+f"(c[0]), "+f"(c[1]), "+f"(c[2]), "+f"(c[3])
        : "r"(a[0]), "r"(a[1]), "r"(a[2]), "r"(a[3]), "r"(b[0]), "r"(b[1]));
}

// ---------------------------------------------------------------------------
// Tensor-core NT GEMM: C[m,o] = sum_k X[m,k] * W[o,k]
// Block tile 128x64, BK=32, 256 threads (8 warps, 4m x 2n of 32x32 warp tiles)
// mode 0: epilogue -> g_Q (scaled)          (W = Wq,  N=512)
// mode 1: epilogue -> g_K / g_V(transposed) (W = Wkv, N=1024)
// mode 2: X = g_A, epilogue -> out + bias   (W = Wo,  N=512)
// ---------------------------------------------------------------------------
__global__ void __launch_bounds__(256) gemm_tc(
    const float* __restrict__ X, const float* __restrict__ W,
    const float* __restrict__ bias, float* __restrict__ out,
    int K, int mode)
{
    __shared__ unsigned As[128][36];   // [m][k] tf32 bits, pad 36 -> conflict-free frags
    __shared__ unsigned Bs[64][36];    // [n][k] tf32 bits

    const float* Xp = (mode == 2) ? g_A : X;

    const int tid  = threadIdx.x;
    const int w    = tid >> 5;
    const int lane = tid & 31;
    const int g    = lane >> 2;
    const int t    = lane & 3;
    const int wm   = (w >> 1) * 32;    // warp m offset (0,32,64,96)
    const int wn   = (w & 1) * 32;     // warp n offset (0,32)
    const int m0   = blockIdx.y * 128;
    const int n0   = blockIdx.x * 64;

    float acc[2][4][4] = {};           // [mt][nt][4]

    for (int k0 = 0; k0 < K; k0 += 32) {
        // Stage X tile 128x32 (1024 float4) and W tile 64x32 (512 float4)
        #pragma unroll
        for (int i = 0; i < 4; i++) {
            int lin = tid + i * 256;
            int r = lin >> 3, c4 = (lin & 7) * 4;
            float4 v = *(const float4*)&Xp[(size_t)(m0 + r) * K + k0 + c4];
            As[r][c4 + 0] = f2tf(v.x); As[r][c4 + 1] = f2tf(v.y);
            As[r][c4 + 2] = f2tf(v.z); As[r][c4 + 3] = f2tf(v.w);
        }
        #pragma unroll
        for (int i = 0; i < 2; i++) {
            int lin = tid + i * 256;
            int r = lin >> 3, c4 = (lin & 7) * 4;
            float4 v = *(const float4*)&W[(size_t)(n0 + r) * K + k0 + c4];
            Bs[r][c4 + 0] = f2tf(v.x); Bs[r][c4 + 1] = f2tf(v.y);
            Bs[r][c4 + 2] = f2tf(v.z); Bs[r][c4 + 3] = f2tf(v.w);
        }
        __syncthreads();

        #pragma unroll
        for (int ks = 0; ks < 4; ks++) {
            int kk = ks * 8;
            unsigned af[2][4], bf[4][2];
            #pragma unroll
            for (int mt = 0; mt < 2; mt++) {
                int r = wm + mt * 16;
                af[mt][0] = As[r + g    ][kk + t];
                af[mt][1] = As[r + g + 8][kk + t];
                af[mt][2] = As[r + g    ][kk + t + 4];
                af[mt][3] = As[r + g + 8][kk + t + 4];
            }
            #pragma unroll
            for (int nt = 0; nt < 4; nt++) {
                bf[nt][0] = Bs[wn + nt * 8 + g][kk + t];
                bf[nt][1] = Bs[wn + nt * 8 + g][kk + t + 4];
            }
            #pragma unroll
            for (int mt = 0; mt < 2; mt++)
                #pragma unroll
                for (int nt = 0; nt < 4; nt++)
                    mma8(acc[mt][nt], af[mt], bf[nt]);
        }
        __syncthreads();
    }

    // Epilogue: C fragment (row g / g+8, cols 2t / 2t+1 per n-tile)
    #pragma unroll
    for (int mt = 0; mt < 2; mt++) {
        #pragma unroll
        for (int rr = 0; rr < 2; rr++) {
            int m = m0 + wm + mt * 16 + g + rr * 8;
            int b = m >> 11, nn = m & 2047;
            #pragma unroll
            for (int nt = 0; nt < 4; nt++) {
                #pragma unroll
                for (int cc = 0; cc < 2; cc++) {
                    int o = n0 + wn + nt * 8 + 2 * t + cc;
                    float v = acc[mt][nt][rr * 2 + cc];
                    if (mode == 0) {
                        int h = o >> 6, d = o & 63;
                        g_Q[(((size_t)(b * Hh + h) * Nn) + nn) * Dd + d] = v * 0.125f;
                    } else if (mode == 1) {
                        if (o < INNER) {
                            int h = o >> 6, d = o & 63;
                            g_K[(((size_t)(b * Hh + h) * Nn) + nn) * Dd + d] = v;
                        } else {
                            int oo = o - INNER;
                            int h = oo >> 6, d = oo & 63;
                            g_V[(((size_t)(b * Hh + h) * Dd) + d) * Nn + nn] = v;
                        }
                    } else {
                        out[(size_t)m * INNER + o] = v + bias[o];
                    }
                }
            }
        }
    }
}

// ---------------------------------------------------------------------------
// Flash attention on tensor cores (tf32).
// Block = 128 queries x one (b,h). 8 warps, each owns 16 query rows.
// Q fragments live in registers for the whole kernel. Key tiles of 32.
// ---------------------------------------------------------------------------
__global__ void __launch_bounds__(256) attn_tc()
{
    __shared__ unsigned Ks[32][68];       // [key][d] tf32
    __shared__ unsigned Vs[64][36];       // [d][key] tf32
    __shared__ unsigned Ps[8][16][36];    // per-warp P [q][key] tf32

    const int tid  = threadIdx.x;
    const int w    = tid >> 5;
    const int lane = tid & 31;
    const int g    = lane >> 2;
    const int t    = lane & 3;
    const int bh   = blockIdx.y;
    const int q0   = blockIdx.x * 128;
    const int qw   = q0 + w * 16;

    // Load Q fragments (pre-scaled fp32 -> tf32). Held for entire kernel.
    unsigned qf[8][4];
    const float* qb = g_Q + ((size_t)bh * Nn + qw) * Dd;
    #pragma unroll
    for (int ks = 0; ks < 8; ks++) {
        int kk = ks * 8;
        qf[ks][0] = f2tf(qb[(g    ) * Dd + kk + t]);
        qf[ks][1] = f2tf(qb[(g + 8) * Dd + kk + t]);
        qf[ks][2] = f2tf(qb[(g    ) * Dd + kk + t + 4]);
        qf[ks][3] = f2tf(qb[(g + 8) * Dd + kk + t + 4]);
    }

    float oacc[8][4] = {};
    float mrun[2] = {-1e30f, -1e30f};
    float lrun[2] = {0.0f, 0.0f};

    for (int t0 = 0; t0 < Nn; t0 += 32) {
        // Stage K tile [32][64] and V tile [64][32]
        #pragma unroll
        for (int i = 0; i < 2; i++) {
            int lin = tid + i * 256;
            int key = lin >> 4, c4 = (lin & 15) * 4;
            float4 v = *(const float4*)&g_K[((size_t)bh * Nn + t0 + key) * Dd + c4];
            Ks[key][c4 + 0] = f2tf(v.x); Ks[key][c4 + 1] = f2tf(v.y);
            Ks[key][c4 + 2] = f2tf(v.z); Ks[key][c4 + 3] = f2tf(v.w);
        }
        #pragma unroll
        for (int i = 0; i < 2; i++) {
            int lin = tid + i * 256;
            int d = lin >> 3, c4 = (lin & 7) * 4;
            float4 v = *(const float4*)&g_V[((size_t)bh * Dd + d) * Nn + t0 + c4];
            Vs[d][c4 + 0] = f2tf(v.x); Vs[d][c4 + 1] = f2tf(v.y);
            Vs[d][c4 + 2] = f2tf(v.z); Vs[d][c4 + 3] = f2tf(v.w);
        }
        __syncthreads();

        // S = Qs @ K^T : 16 x 32 per warp (4 n-tiles), k over d=64 (8 steps)
        float sacc[4][4] = {};
        #pragma unroll
        for (int ks = 0; ks < 8; ks++) {
            int kk = ks * 8;
            unsigned bf[4][2];
            #pragma unroll
            for (int nt = 0; nt < 4; nt++) {
                bf[nt][0] = Ks[nt * 8 + g][kk + t];
                bf[nt][1] = Ks[nt * 8 + g][kk + t + 4];
            }
            #pragma unroll
            for (int nt = 0; nt < 4; nt++)
                mma8(sacc[nt], qf[ks], bf[nt]);
        }

        // Online softmax. Thread owns rows g (regs 0,1) and g+8 (regs 2,3).
        float rm0 = -1e30f, rm1 = -1e30f;
        #pragma unroll
        for (int nt = 0; nt < 4; nt++) {
            rm0 = fmaxf(rm0, fmaxf(sacc[nt][0], sacc[nt][1]));
            rm1 = fmaxf(rm1, fmaxf(sacc[nt][2], sacc[nt][3]));
        }
        #pragma unroll
        for (int off = 1; off < 4; off <<= 1) {
            rm0 = fmaxf(rm0, __shfl_xor_sync(0xffffffffu, rm0, off, 4));
            rm1 = fmaxf(rm1, __shfl_xor_sync(0xffffffffu, rm1, off, 4));
        }
        float mn0 = fmaxf(mrun[0], rm0), mn1 = fmaxf(mrun[1], rm1);
        float corr0 = __expf(mrun[0] - mn0), corr1 = __expf(mrun[1] - mn1);
        mrun[0] = mn0; mrun[1] = mn1;

        float rs0 = 0.0f, rs1 = 0.0f;
        #pragma unroll
        for (int nt = 0; nt < 4; nt++) {
            float p0 = __expf(sacc[nt][0] - mn0);
            float p1 = __expf(sacc[nt][1] - mn0);
            float p2 = __expf(sacc[nt][2] - mn1);
            float p3 = __expf(sacc[nt][3] - mn1);
            rs0 += p0 + p1; rs1 += p2 + p3;
            int c = nt * 8 + 2 * t;
            Ps[w][g    ][c] = f2tf(p0); Ps[w][g    ][c + 1] = f2tf(p1);
            Ps[w][g + 8][c] = f2tf(p2); Ps[w][g + 8][c + 1] = f2tf(p3);
        }
        #pragma unroll
        for (int off = 1; off < 4; off <<= 1) {
            rs0 += __shfl_xor_sync(0xffffffffu, rs0, off, 4);
            rs1 += __shfl_xor_sync(0xffffffffu, rs1, off, 4);
        }
        lrun[0] = lrun[0] * corr0 + rs0;
        lrun[1] = lrun[1] * corr1 + rs1;
        #pragma unroll
        for (int nt = 0; nt < 8; nt++) {
            oacc[nt][0] *= corr0; oacc[nt][1] *= corr0;
            oacc[nt][2] *= corr1; oacc[nt][3] *= corr1;
        }
        __syncwarp();   // Ps[w] is warp-private: write->read ordering

        // O += P @ V : m16 x n64 (8 n-tiles over d), k over 32 keys (4 steps)
        #pragma unroll
        for (int ks = 0; ks < 4; ks++) {
            int kk = ks * 8;
            unsigned af[4];
            af[0] = Ps[w][g    ][kk + t];
            af[1] = Ps[w][g + 8][kk + t];
            af[2] = Ps[w][g    ][kk + t + 4];
            af[3] = Ps[w][g + 8][kk + t + 4];
            #pragma unroll
            for (int nt = 0; nt < 8; nt++) {
                unsigned bf2[2];
                bf2[0] = Vs[nt * 8 + g][kk + t];
                bf2[1] = Vs[nt * 8 + g][kk + t + 4];
                mma8(oacc[nt], af, bf2);
            }
        }
        __syncthreads();   // before next tile overwrites Ks/Vs
    }

    // Normalize and store to g_A[m][h*64+d]
    const int b = bh >> 3, h = bh & 7;
    float inv0 = 1.0f / lrun[0], inv1 = 1.0f / lrun[1];
    size_t r0 = ((size_t)b * Nn + qw + g    ) * INNER + h * 64;
    size_t r1 = ((size_t)b * Nn + qw + g + 8) * INNER + h * 64;
    #pragma unroll
    for (int nt = 0; nt < 8; nt++) {
        int c = nt * 8 + 2 * t;
        g_A[r0 + c]     = oacc[nt][0] * inv0;
        g_A[r0 + c + 1] = oacc[nt][1] * inv0;
        g_A[r1 + c]     = oacc[nt][2] * inv1;
        g_A[r1 + c + 1] = oacc[nt][3] * inv1;
    }
}

// ---------------------------------------------------------------------------
extern "C" void kernel_launch(void* const* d_in, const int* in_sizes, int n_in,
                              void* d_out, int out_size)
{
    const float* x   = (const float*)d_in[0];
    const float* Wq  = (const float*)d_in[1];
    const float* Wkv = (const float*)d_in[2];
    const float* Wo  = (const float*)d_in[3];
    const float* bo  = (const float*)d_in[4];
    float* out = (float*)d_out;

    dim3 thr(256);

    // Q projection: N=512
    gemm_tc<<<dim3(INNER / 64, M_TOT / 128), thr>>>(x, Wq, nullptr, nullptr, INDIM, 0);
    // KV projection: N=1024
    gemm_tc<<<dim3(2 * INNER / 64, M_TOT / 128), thr>>>(x, Wkv, nullptr, nullptr, INDIM, 1);
    // Attention: 16 q-tiles x 32 (b,h)
    attn_tc<<<dim3(Nn / 128, Bb * Hh), thr>>>();
    // Output projection + bias: N=512
    gemm_tc<<<dim3(INDIM / 64, M_TOT / 128), thr>>>(nullptr, Wo, bo, out, INNER, 2);
}

// round 5
// speedup vs baseline: 3.4670x; 1.2458x over previous
#include <cuda_runtime.h>

// Problem constants
#define Hh     8
#define Dd     64
#define INDIM  512
#define Bb     4
#define Nn     2048
#define INNER  512            // H*D
#define M_TOT  (Bb*Nn)        // 8192

// Scratch (allocation-free: __device__ globals). All hold tf32-rounded bits.
__device__ __align__(16) float g_X  [(size_t)M_TOT*INDIM];
__device__ __align__(16) float g_Wq [(size_t)INNER*INDIM];
__device__ __align__(16) float g_Wkv[(size_t)2*INNER*INDIM];
__device__ __align__(16) float g_Wo [(size_t)INDIM*INNER];
__device__ __align__(16) float g_Q  [(size_t)Bb*Hh*Nn*Dd];  // [bh][n][d], pre-scaled 0.125
__device__ __align__(16) float g_K  [(size_t)Bb*Hh*Nn*Dd];  // [bh][n][d]
__device__ __align__(16) float g_V  [(size_t)Bb*Hh*Dd*Nn];  // [bh][d][n] (transposed)
__device__ __align__(16) float g_A  [(size_t)M_TOT*INNER];  // [m][o]

// ---------------------------------------------------------------------------
// Helpers
// ---------------------------------------------------------------------------
__device__ __forceinline__ unsigned f2tf(float f) {
    unsigned u;
    asm("cvt.rna.tf32.f32 %0, %1;" : "=r"(u) : "f"(f));
    return u;
}
__device__ __forceinline__ float tfr(float f) { return __uint_as_float(f2tf(f)); }

__device__ __forceinline__ void mma8(float c[4], const unsigned a[4], const unsigned b[2]) {
    asm volatile(
        "mma.sync.aligned.m16n8k8.row.col.f32.tf32.tf32.f32 "
        "{%0,%1,%2,%3},{%4,%5,%6,%7},{%8,%9},{%0,%1,%2,%3};"
        : "+f"(c[0]), "+f"(c[1]), "+f"(c[2]), "+f"(c[3])
        : "r"(a[0]), "r"(a[1]), "r"(a[2]), "r"(a[3]), "r"(b[0]), "r"(b[1]));
}

__device__ __forceinline__ void cpa16(unsigned dst, const void* src) {
    asm volatile("cp.async.ca.shared.global [%0], [%1], 16;" :: "r"(dst), "l"(src));
}
#define CP_COMMIT() asm volatile("cp.async.commit_group;" ::: "memory")
#define CP_WAIT0()  asm volatile("cp.async.wait_group 0;" ::: "memory")
#define CP_WAIT1()  asm volatile("cp.async.wait_group 1;" ::: "memory")

// ---------------------------------------------------------------------------
// Prep: round x / Wq / Wkv / Wo to tf32 bits once.
// ---------------------------------------------------------------------------
__global__ void __launch_bounds__(256) prep(
    const float4* __restrict__ x, const float4* __restrict__ wq,
    const float4* __restrict__ wkv, const float4* __restrict__ wo)
{
    const size_t nx  = (size_t)M_TOT * INDIM / 4;
    const size_t nq  = (size_t)INNER * INDIM / 4;
    const size_t nkv = (size_t)2 * INNER * INDIM / 4;
    const size_t no  = (size_t)INDIM * INNER / 4;
    const size_t total = nx + nq + nkv + no;
    for (size_t i = blockIdx.x * 256 + threadIdx.x; i < total; i += gridDim.x * 256) {
        const float4* src; float4* dst; size_t j = i;
        if (j < nx)              { src = x;   dst = (float4*)g_X; }
        else if ((j -= nx) < nq) { src = wq;  dst = (float4*)g_Wq; }
        else if ((j -= nq) < nkv){ src = wkv; dst = (float4*)g_Wkv; }
        else          { j -= nkv;  src = wo;  dst = (float4*)g_Wo; }
        float4 v = src[j];
        v.x = tfr(v.x); v.y = tfr(v.y); v.z = tfr(v.z); v.w = tfr(v.w);
        dst[j] = v;
    }
}

// ---------------------------------------------------------------------------
// Pipelined TC GEMM: C[m,o] = sum_k X[m,k]*W[o,k], K=512 fixed.
// 128x128 block tile, BK=32, 3-stage cp.async. 8 warps = 2(m) x 4(n),
// warp tile 64x32. Smem pad 36 -> conflict-free fragment LDS.
// ---------------------------------------------------------------------------
#define GSTG 3
#define ATILE (128*36)

__global__ void __launch_bounds__(256, 2) gemm_tc(
    const float* __restrict__ bias, float* __restrict__ out, int mode)
{
    extern __shared__ unsigned sm[];
    unsigned* As = sm;                 // [GSTG][128][36]
    unsigned* Bs = sm + GSTG * ATILE;  // [GSTG][128][36]

    const unsigned* Xp; const unsigned* Wp;
    if (mode == 0)      { Xp = (const unsigned*)g_X; Wp = (const unsigned*)g_Wq; }
    else if (mode == 1) { Xp = (const unsigned*)g_X; Wp = (const unsigned*)g_Wkv; }
    else                { Xp = (const unsigned*)g_A; Wp = (const unsigned*)g_Wo; }

    const int tid  = threadIdx.x;
    const int w    = tid >> 5;
    const int lane = tid & 31;
    const int g    = lane >> 2;
    const int t    = lane & 3;
    const int wm   = (w & 1) * 64;
    const int wn   = (w >> 1) * 32;
    const int m0   = blockIdx.y * 128;
    const int n0   = blockIdx.x * 128;

    const unsigned sA = (unsigned)__cvta_generic_to_shared(As);
    const unsigned sB = (unsigned)__cvta_generic_to_shared(Bs);

    float acc[4][4][4] = {};   // [mt][nt][4]

    auto issue = [&](int s, int k0) {
        #pragma unroll
        for (int j = 0; j < 4; j++) {
            int chunk = tid + j * 256;
            int r = chunk >> 3, c = (chunk & 7) * 4;
            cpa16(sA + ((s * 128 + r) * 36 + c) * 4, Xp + (size_t)(m0 + r) * INDIM + k0 + c);
            cpa16(sB + ((s * 128 + r) * 36 + c) * 4, Wp + (size_t)(n0 + r) * INDIM + k0 + c);
        }
        CP_COMMIT();
    };

    issue(0, 0);
    issue(1, 32);

    #pragma unroll 1
    for (int i = 0; i < 16; i++) {
        if (i < 14) { CP_WAIT1(); } else { CP_WAIT0(); }
        __syncthreads();
        if (i + 2 < 16) issue((i + 2) % GSTG, (i + 2) * 32);

        const unsigned* Abuf = As + (i % GSTG) * ATILE;
        const unsigned* Bbuf = Bs + (i % GSTG) * ATILE;
        #pragma unroll
        for (int ks = 0; ks < 4; ks++) {
            int kk = ks * 8;
            unsigned af[4][4], bf[4][2];
            #pragma unroll
            for (int mt = 0; mt < 4; mt++) {
                int r = wm + mt * 16;
                af[mt][0] = Abuf[(r + g    ) * 36 + kk + t];
                af[mt][1] = Abuf[(r + g + 8) * 36 + kk + t];
                af[mt][2] = Abuf[(r + g    ) * 36 + kk + t + 4];
                af[mt][3] = Abuf[(r + g + 8) * 36 + kk + t + 4];
            }
            #pragma unroll
            for (int nt = 0; nt < 4; nt++) {
                bf[nt][0] = Bbuf[(wn + nt * 8 + g) * 36 + kk + t];
                bf[nt][1] = Bbuf[(wn + nt * 8 + g) * 36 + kk + t + 4];
            }
            #pragma unroll
            for (int mt = 0; mt < 4; mt++)
                #pragma unroll
                for (int nt = 0; nt < 4; nt++)
                    mma8(acc[mt][nt], af[mt], bf[nt]);
        }
        __syncthreads();
    }

    // Epilogue
    #pragma unroll
    for (int mt = 0; mt < 4; mt++) {
        #pragma unroll
        for (int rr = 0; rr < 2; rr++) {
            int m = m0 + wm + mt * 16 + g + rr * 8;
            int bb = m >> 11, nn = m & 2047;
            #pragma unroll
            for (int nt = 0; nt < 4; nt++) {
                #pragma unroll
                for (int cc = 0; cc < 2; cc++) {
                    int o = n0 + wn + nt * 8 + 2 * t + cc;
                    float v = acc[mt][nt][rr * 2 + cc];
                    if (mode == 0) {
                        int h = o >> 6, d = o & 63;
                        g_Q[(((size_t)(bb * Hh + h) * Nn) + nn) * Dd + d] = tfr(v * 0.125f);
                    } else if (mode == 1) {
                        if (o < INNER) {
                            int h = o >> 6, d = o & 63;
                            g_K[(((size_t)(bb * Hh + h) * Nn) + nn) * Dd + d] = tfr(v);
                        } else {
                            int oo = o - INNER;
                            int h = oo >> 6, d = oo & 63;
                            g_V[(((size_t)(bb * Hh + h) * Dd) + d) * Nn + nn] = tfr(v);
                        }
                    } else {
                        out[(size_t)m * INNER + o] = v + bias[o];
                    }
                }
            }
        }
    }
}

// ---------------------------------------------------------------------------
// Flash attention, tf32 TC, 2-stage cp.async on 64-key tiles.
// Block = 128 queries x one (b,h). 8 warps x 16 q rows. Q frags in regs.
// Smem: Ks[2][64][68], Vs[2][64][68], Ps[8][16][68]  (P rows 68-wide!)
// ---------------------------------------------------------------------------
#define KTILE (64*68)
#define PSTR  68
#define PROWS (16*PSTR)

__global__ void __launch_bounds__(256, 2) attn_tc()
{
    extern __shared__ unsigned sm[];
    unsigned* Ks = sm;                    // 2*64*68
    unsigned* Vs = sm + 2 * KTILE;        // 2*64*68
    unsigned* Ps = sm + 4 * KTILE;        // 8*16*68

    const int tid  = threadIdx.x;
    const int w    = tid >> 5;
    const int lane = tid & 31;
    const int g    = lane >> 2;
    const int t    = lane & 3;
    const int bh   = blockIdx.y;
    const int qw   = blockIdx.x * 128 + w * 16;

    const unsigned sK = (unsigned)__cvta_generic_to_shared(Ks);
    const unsigned sV = (unsigned)__cvta_generic_to_shared(Vs);
    const unsigned* gK = (const unsigned*)g_K;
    const unsigned* gV = (const unsigned*)g_V;

    // Q fragments, resident all kernel
    unsigned qf[8][4];
    {
        const unsigned* qb = (const unsigned*)g_Q + ((size_t)bh * Nn + qw) * Dd;
        #pragma unroll
        for (int ks = 0; ks < 8; ks++) {
            int kk = ks * 8;
            qf[ks][0] = qb[(g    ) * Dd + kk + t];
            qf[ks][1] = qb[(g + 8) * Dd + kk + t];
            qf[ks][2] = qb[(g    ) * Dd + kk + t + 4];
            qf[ks][3] = qb[(g + 8) * Dd + kk + t + 4];
        }
    }

    auto issue = [&](int s, int t0) {
        #pragma unroll
        for (int j = 0; j < 4; j++) {
            int chunk = tid + j * 256;
            int r = chunk >> 4, c = (chunk & 15) * 4;
            cpa16(sK + ((s * 64 + r) * 68 + c) * 4,
                  gK + ((size_t)bh * Nn + t0 + r) * Dd + c);
            cpa16(sV + ((s * 64 + r) * 68 + c) * 4,
                  gV + ((size_t)bh * Dd + r) * Nn + t0 + c);
        }
        CP_COMMIT();
    };

    float oacc[8][4] = {};
    float mrun[2] = {-1e30f, -1e30f};
    float lrun[2] = {0.0f, 0.0f};

    issue(0, 0);

    #pragma unroll 1
    for (int i = 0; i < 32; i++) {
        CP_WAIT0();
        __syncthreads();
        if (i + 1 < 32) issue((i + 1) & 1, (i + 1) * 64);

        const unsigned* Kbuf = Ks + (i & 1) * KTILE;
        const unsigned* Vbuf = Vs + (i & 1) * KTILE;

        // S = Qs @ K^T : 16 x 64 per warp, k over d (8 steps)
        float sacc[8][4] = {};
        #pragma unroll
        for (int ks = 0; ks < 8; ks++) {
            int kk = ks * 8;
            unsigned bf[8][2];
            #pragma unroll
            for (int nt = 0; nt < 8; nt++) {
                bf[nt][0] = Kbuf[(nt * 8 + g) * 68 + kk + t];
                bf[nt][1] = Kbuf[(nt * 8 + g) * 68 + kk + t + 4];
            }
            #pragma unroll
            for (int nt = 0; nt < 8; nt++)
                mma8(sacc[nt], qf[ks], bf[nt]);
        }

        // Online softmax; thread owns rows g (regs 0,1) and g+8 (regs 2,3)
        float rm0 = -1e30f, rm1 = -1e30f;
        #pragma unroll
        for (int nt = 0; nt < 8; nt++) {
            rm0 = fmaxf(rm0, fmaxf(sacc[nt][0], sacc[nt][1]));
            rm1 = fmaxf(rm1, fmaxf(sacc[nt][2], sacc[nt][3]));
        }
        #pragma unroll
        for (int off = 1; off < 4; off <<= 1) {
            rm0 = fmaxf(rm0, __shfl_xor_sync(0xffffffffu, rm0, off, 4));
            rm1 = fmaxf(rm1, __shfl_xor_sync(0xffffffffu, rm1, off, 4));
        }
        float mn0 = fmaxf(mrun[0], rm0), mn1 = fmaxf(mrun[1], rm1);
        float corr0 = __expf(mrun[0] - mn0), corr1 = __expf(mrun[1] - mn1);
        mrun[0] = mn0; mrun[1] = mn1;

        unsigned* Pw = Ps + w * PROWS;
        float rs0 = 0.0f, rs1 = 0.0f;
        #pragma unroll
        for (int nt = 0; nt < 8; nt++) {
            float p0 = __expf(sacc[nt][0] - mn0);
            float p1 = __expf(sacc[nt][1] - mn0);
            float p2 = __expf(sacc[nt][2] - mn1);
            float p3 = __expf(sacc[nt][3] - mn1);
            rs0 += p0 + p1; rs1 += p2 + p3;
            int c = nt * 8 + 2 * t;
            Pw[(g    ) * PSTR + c]     = f2tf(p0);
            Pw[(g    ) * PSTR + c + 1] = f2tf(p1);
            Pw[(g + 8) * PSTR + c]     = f2tf(p2);
            Pw[(g + 8) * PSTR + c + 1] = f2tf(p3);
        }
        #pragma unroll
        for (int off = 1; off < 4; off <<= 1) {
            rs0 += __shfl_xor_sync(0xffffffffu, rs0, off, 4);
            rs1 += __shfl_xor_sync(0xffffffffu, rs1, off, 4);
        }
        lrun[0] = lrun[0] * corr0 + rs0;
        lrun[1] = lrun[1] * corr1 + rs1;
        #pragma unroll
        for (int nt = 0; nt < 8; nt++) {
            oacc[nt][0] *= corr0; oacc[nt][1] *= corr0;
            oacc[nt][2] *= corr1; oacc[nt][3] *= corr1;
        }
        __syncwarp();   // Ps is warp-private

        // O += P @ V : n over d (8 tiles), k over 64 keys (8 steps)
        #pragma unroll
        for (int ks = 0; ks < 8; ks++) {
            int kk = ks * 8;
            unsigned af[4];
            af[0] = Pw[(g    ) * PSTR + kk + t];
            af[1] = Pw[(g + 8) * PSTR + kk + t];
            af[2] = Pw[(g    ) * PSTR + kk + t + 4];
            af[3] = Pw[(g + 8) * PSTR + kk + t + 4];
            #pragma unroll
            for (int nt = 0; nt < 8; nt++) {
                unsigned bf2[2];
                bf2[0] = Vbuf[(nt * 8 + g) * 68 + kk + t];
                bf2[1] = Vbuf[(nt * 8 + g) * 68 + kk + t + 4];
                mma8(oacc[nt], af, bf2);
            }
        }
    }

    // Normalize, round to tf32, store to g_A[m][h*64+d]
    const int bb = bh >> 3, h = bh & 7;
    float inv0 = 1.0f / lrun[0], inv1 = 1.0f / lrun[1];
    size_t r0 = ((size_t)bb * Nn + qw + g    ) * INNER + h * 64;
    size_t r1 = ((size_t)bb * Nn + qw + g + 8) * INNER + h * 64;
    #pragma unroll
    for (int nt = 0; nt < 8; nt++) {
        int c = nt * 8 + 2 * t;
        g_A[r0 + c]     = tfr(oacc[nt][0] * inv0);
        g_A[r0 + c + 1] = tfr(oacc[nt][1] * inv0);
        g_A[r1 + c]     = tfr(oacc[nt][2] * inv1);
        g_A[r1 + c + 1] = tfr(oacc[nt][3] * inv1);
    }
}

// ---------------------------------------------------------------------------
extern "C" void kernel_launch(void* const* d_in, const int* in_sizes, int n_in,
                              void* d_out, int out_size)
{
    const float* x   = (const float*)d_in[0];
    const float* Wq  = (const float*)d_in[1];
    const float* Wkv = (const float*)d_in[2];
    const float* Wo  = (const float*)d_in[3];
    const float* bo  = (const float*)d_in[4];
    float* out = (float*)d_out;

    const int gemmSmem = GSTG * ATILE * 4 * 2;                 // 110592
    const int attnSmem = (4 * KTILE + 8 * PROWS) * 4;          // 104448

    cudaFuncSetAttribute(gemm_tc, cudaFuncAttributeMaxDynamicSharedMemorySize, gemmSmem);
    cudaFuncSetAttribute(attn_tc, cudaFuncAttributeMaxDynamicSharedMemorySize, attnSmem);

    prep<<<1024, 256>>>((const float4*)x, (const float4*)Wq,
                        (const float4*)Wkv, (const float4*)Wo);
    gemm_tc<<<dim3(INNER / 128, M_TOT / 128), 256, gemmSmem>>>(nullptr, nullptr, 0);
    gemm_tc<<<dim3(2 * INNER / 128, M_TOT / 128), 256, gemmSmem>>>(nullptr, nullptr, 1);
    attn_tc<<<dim3(Nn / 128, Bb * Hh), 256, attnSmem>>>();
    gemm_tc<<<dim3(INDIM / 128, M_TOT / 128), 256, gemmSmem>>>(bo, out, 2);
}

// round 6
// speedup vs baseline: 6.1164x; 1.7641x over previous
#include <cuda_runtime.h>
#include <cuda_fp16.h>

// Problem constants
#define Hh     8
#define Dd     64
#define INDIM  512
#define Bb     4
#define Nn     2048
#define INNER  512            // H*D
#define M_TOT  (Bb*Nn)        // 8192

// Scratch (allocation-free: __device__ globals). fp16 operands, fp32 accum.
__device__ __align__(16) __half g_X  [(size_t)M_TOT*INDIM];
__device__ __align__(16) __half g_Wq [(size_t)INNER*INDIM];
__device__ __align__(16) __half g_Wkv[(size_t)2*INNER*INDIM];
__device__ __align__(16) __half g_Wo [(size_t)INDIM*INNER];
__device__ __align__(16) __half g_Q  [(size_t)Bb*Hh*Nn*Dd];  // [bh][n][d], pre-scaled 0.125
__device__ __align__(16) __half g_K  [(size_t)Bb*Hh*Nn*Dd];  // [bh][n][d]
__device__ __align__(16) __half g_V  [(size_t)Bb*Hh*Dd*Nn];  // [bh][d][n] (transposed)
__device__ __align__(16) __half g_A  [(size_t)M_TOT*INNER];  // [m][o]

// ---------------------------------------------------------------------------
// Helpers
// ---------------------------------------------------------------------------
// D += A*B, m16n8k16, A row-major, B col-major, f16 in, f32 acc.
__device__ __forceinline__ void mma16(float c[4], const unsigned a[4], const unsigned b[2]) {
    asm volatile(
        "mma.sync.aligned.m16n8k16.row.col.f32.f16.f16.f32 "
        "{%0,%1,%2,%3},{%4,%5,%6,%7},{%8,%9},{%0,%1,%2,%3};"
        : "+f"(c[0]), "+f"(c[1]), "+f"(c[2]), "+f"(c[3])
        : "r"(a[0]), "r"(a[1]), "r"(a[2]), "r"(a[3]), "r"(b[0]), "r"(b[1]));
}

__device__ __forceinline__ void cpa16(unsigned dst, const void* src) {
    asm volatile("cp.async.ca.shared.global [%0], [%1], 16;" :: "r"(dst), "l"(src));
}
#define CP_COMMIT() asm volatile("cp.async.commit_group;" ::: "memory")
#define CP_WAIT0()  asm volatile("cp.async.wait_group 0;" ::: "memory")
#define CP_WAIT1()  asm volatile("cp.async.wait_group 1;" ::: "memory")

__device__ __forceinline__ unsigned pack2(float a, float b) {
    __half2 h = __floats2half2_rn(a, b);
    return *(unsigned*)&h;
}

// ---------------------------------------------------------------------------
// Prep: convert x / Wq / Wkv / Wo to fp16.
// ---------------------------------------------------------------------------
__global__ void __launch_bounds__(256) prep(
    const float4* __restrict__ x, const float4* __restrict__ wq,
    const float4* __restrict__ wkv, const float4* __restrict__ wo)
{
    const size_t nx  = (size_t)M_TOT * INDIM / 4;
    const size_t nq  = (size_t)INNER * INDIM / 4;
    const size_t nkv = (size_t)2 * INNER * INDIM / 4;
    const size_t no  = (size_t)INDIM * INNER / 4;
    const size_t total = nx + nq + nkv + no;
    for (size_t i = blockIdx.x * 256 + threadIdx.x; i < total; i += gridDim.x * 256) {
        const float4* src; __half2* dst; size_t j = i;
        if (j < nx)              { src = x;   dst = (__half2*)g_X; }
        else if ((j -= nx) < nq) { src = wq;  dst = (__half2*)g_Wq; }
        else if ((j -= nq) < nkv){ src = wkv; dst = (__half2*)g_Wkv; }
        else          { j -= nkv;  src = wo;  dst = (__half2*)g_Wo; }
        float4 v = src[j];
        dst[j * 2]     = __floats2half2_rn(v.x, v.y);
        dst[j * 2 + 1] = __floats2half2_rn(v.z, v.w);
    }
}

// ---------------------------------------------------------------------------
// Pipelined fp16 TC GEMM: C[m,o] = sum_k X[m,k]*W[o,k], K=512.
// 128x128 block tile, BK=64 halfs, 3-stage cp.async. 8 warps = 2(m) x 4(n),
// warp tile 64x32. Smem rows 72 halfs (36 words) -> conflict-free frag LDS.
// mode 0: -> g_Q (x0.125)   mode 1: -> g_K/g_V   mode 2: X=g_A -> out+bias
// ---------------------------------------------------------------------------
#define GSTG 3
#define GROWW 36                 // words per smem row (72 halfs)
#define ATILEW (128*GROWW)       // words per tile

__global__ void __launch_bounds__(256, 2) gemm_tc(
    const float* __restrict__ bias, float* __restrict__ out, int mode)
{
    extern __shared__ unsigned sm[];
    unsigned* As = sm;                  // [GSTG][128][36] words
    unsigned* Bs = sm + GSTG * ATILEW;  // [GSTG][128][36] words

    const __half* Xp; const __half* Wp;
    if (mode == 0)      { Xp = g_X; Wp = g_Wq; }
    else if (mode == 1) { Xp = g_X; Wp = g_Wkv; }
    else                { Xp = g_A; Wp = g_Wo; }

    const int tid  = threadIdx.x;
    const int w    = tid >> 5;
    const int lane = tid & 31;
    const int g    = lane >> 2;
    const int t    = lane & 3;
    const int wm   = (w & 1) * 64;
    const int wn   = (w >> 1) * 32;
    const int m0   = blockIdx.y * 128;
    const int n0   = blockIdx.x * 128;

    const unsigned sA = (unsigned)__cvta_generic_to_shared(As);
    const unsigned sB = (unsigned)__cvta_generic_to_shared(Bs);

    float acc[4][4][4] = {};   // [mt][nt][4]

    // stage: 128x64 halfs A + B. 1024 chunks of 8 halfs each per tile.
    auto issue = [&](int s, int k0) {
        #pragma unroll
        for (int j = 0; j < 4; j++) {
            int chunk = tid + j * 256;
            int r = chunk >> 3, c = (chunk & 7) * 8;   // c in halfs
            cpa16(sA + ((s * 128 + r) * GROWW + c / 2) * 4,
                  Xp + (size_t)(m0 + r) * INDIM + k0 + c);
            cpa16(sB + ((s * 128 + r) * GROWW + c / 2) * 4,
                  Wp + (size_t)(n0 + r) * INDIM + k0 + c);
        }
        CP_COMMIT();
    };

    issue(0, 0);
    issue(1, 64);

    #pragma unroll 1
    for (int i = 0; i < 8; i++) {
        if (i < 6) { CP_WAIT1(); } else { CP_WAIT0(); }
        __syncthreads();
        if (i + 2 < 8) issue((i + 2) % GSTG, (i + 2) * 64);

        const unsigned* Abuf = As + (i % GSTG) * ATILEW;
        const unsigned* Bbuf = Bs + (i % GSTG) * ATILEW;
        #pragma unroll
        for (int ks = 0; ks < 4; ks++) {            // k16 steps
            int kw = ks * 8;                         // word offset
            unsigned af[4][4], bf[4][2];
            #pragma unroll
            for (int mt = 0; mt < 4; mt++) {
                int r = wm + mt * 16;
                af[mt][0] = Abuf[(r + g    ) * GROWW + kw + t];
                af[mt][1] = Abuf[(r + g + 8) * GROWW + kw + t];
                af[mt][2] = Abuf[(r + g    ) * GROWW + kw + t + 4];
                af[mt][3] = Abuf[(r + g + 8) * GROWW + kw + t + 4];
            }
            #pragma unroll
            for (int nt = 0; nt < 4; nt++) {
                bf[nt][0] = Bbuf[(wn + nt * 8 + g) * GROWW + kw + t];
                bf[nt][1] = Bbuf[(wn + nt * 8 + g) * GROWW + kw + t + 4];
            }
            #pragma unroll
            for (int mt = 0; mt < 4; mt++)
                #pragma unroll
                for (int nt = 0; nt < 4; nt++)
                    mma16(acc[mt][nt], af[mt], bf[nt]);
        }
        __syncthreads();
    }

    // Epilogue
    #pragma unroll
    for (int mt = 0; mt < 4; mt++) {
        #pragma unroll
        for (int rr = 0; rr < 2; rr++) {
            int m = m0 + wm + mt * 16 + g + rr * 8;
            int bb = m >> 11, nn = m & 2047;
            #pragma unroll
            for (int nt = 0; nt < 4; nt++) {
                #pragma unroll
                for (int cc = 0; cc < 2; cc++) {
                    int o = n0 + wn + nt * 8 + 2 * t + cc;
                    float v = acc[mt][nt][rr * 2 + cc];
                    if (mode == 0) {
                        int h = o >> 6, d = o & 63;
                        g_Q[(((size_t)(bb * Hh + h) * Nn) + nn) * Dd + d] =
                            __float2half_rn(v * 0.125f);
                    } else if (mode == 1) {
                        if (o < INNER) {
                            int h = o >> 6, d = o & 63;
                            g_K[(((size_t)(bb * Hh + h) * Nn) + nn) * Dd + d] =
                                __float2half_rn(v);
                        } else {
                            int oo = o - INNER;
                            int h = oo >> 6, d = oo & 63;
                            g_V[(((size_t)(bb * Hh + h) * Dd) + d) * Nn + nn] =
                                __float2half_rn(v);
                        }
                    } else {
                        out[(size_t)m * INNER + o] = v + bias[o];
                    }
                }
            }
        }
    }
}

// ---------------------------------------------------------------------------
// Flash attention, fp16 TC, 2-stage cp.async on 64-key tiles.
// Block = 128 queries x one (b,h). 8 warps x 16 q rows. Q frags in regs.
// Smem (halfs): Ks[2][64][72], Vs[2][64][72], Ps[8][16][72].
// ---------------------------------------------------------------------------
#define KROWW 36                 // words per K/V/P smem row (72 halfs)
#define KTILEW (64*KROWW)        // words per K or V tile
#define PROWSW (16*KROWW)        // words per warp's P block

__global__ void __launch_bounds__(256, 2) attn_tc()
{
    extern __shared__ unsigned sm[];
    unsigned* Ks = sm;                     // 2*KTILEW
    unsigned* Vs = sm + 2 * KTILEW;        // 2*KTILEW
    unsigned* Ps = sm + 4 * KTILEW;        // 8*PROWSW

    const int tid  = threadIdx.x;
    const int w    = tid >> 5;
    const int lane = tid & 31;
    const int g    = lane >> 2;
    const int t    = lane & 3;
    const int bh   = blockIdx.y;
    const int qw   = blockIdx.x * 128 + w * 16;

    const unsigned sK = (unsigned)__cvta_generic_to_shared(Ks);
    const unsigned sV = (unsigned)__cvta_generic_to_shared(Vs);

    // Q fragments (words of half2), resident all kernel. 4 k16 steps over d=64.
    unsigned qf[4][4];
    {
        const unsigned* qb = (const unsigned*)g_Q + ((size_t)bh * Nn + qw) * (Dd / 2);
        #pragma unroll
        for (int ks = 0; ks < 4; ks++) {
            int kw = ks * 8;
            qf[ks][0] = qb[(g    ) * 32 + kw + t];
            qf[ks][1] = qb[(g + 8) * 32 + kw + t];
            qf[ks][2] = qb[(g    ) * 32 + kw + t + 4];
            qf[ks][3] = qb[(g + 8) * 32 + kw + t + 4];
        }
    }

    auto issue = [&](int s, int t0) {
        #pragma unroll
        for (int j = 0; j < 2; j++) {
            int chunk = tid + j * 256;                 // 512 chunks per tile
            int r = chunk >> 3, c = (chunk & 7) * 8;   // c in halfs
            cpa16(sK + ((s * 64 + r) * KROWW + c / 2) * 4,
                  g_K + ((size_t)bh * Nn + t0 + r) * Dd + c);
            cpa16(sV + ((s * 64 + r) * KROWW + c / 2) * 4,
                  g_V + ((size_t)bh * Dd + r) * Nn + t0 + c);
        }
        CP_COMMIT();
    };

    float oacc[8][4] = {};
    float mrun[2] = {-1e30f, -1e30f};
    float lrun[2] = {0.0f, 0.0f};

    issue(0, 0);

    #pragma unroll 1
    for (int i = 0; i < 32; i++) {
        CP_WAIT0();
        __syncthreads();
        if (i + 1 < 32) issue((i + 1) & 1, (i + 1) * 64);

        const unsigned* Kbuf = Ks + (i & 1) * KTILEW;
        const unsigned* Vbuf = Vs + (i & 1) * KTILEW;

        // S = Qs @ K^T : 16 x 64 per warp, 4 k16 steps over d
        float sacc[8][4] = {};
        #pragma unroll
        for (int ks = 0; ks < 4; ks++) {
            int kw = ks * 8;
            unsigned bf[8][2];
            #pragma unroll
            for (int nt = 0; nt < 8; nt++) {
                bf[nt][0] = Kbuf[(nt * 8 + g) * KROWW + kw + t];
                bf[nt][1] = Kbuf[(nt * 8 + g) * KROWW + kw + t + 4];
            }
            #pragma unroll
            for (int nt = 0; nt < 8; nt++)
                mma16(sacc[nt], qf[ks], bf[nt]);
        }

        // Online softmax; thread owns rows g (regs 0,1) and g+8 (regs 2,3)
        float rm0 = -1e30f, rm1 = -1e30f;
        #pragma unroll
        for (int nt = 0; nt < 8; nt++) {
            rm0 = fmaxf(rm0, fmaxf(sacc[nt][0], sacc[nt][1]));
            rm1 = fmaxf(rm1, fmaxf(sacc[nt][2], sacc[nt][3]));
        }
        #pragma unroll
        for (int off = 1; off < 4; off <<= 1) {
            rm0 = fmaxf(rm0, __shfl_xor_sync(0xffffffffu, rm0, off, 4));
            rm1 = fmaxf(rm1, __shfl_xor_sync(0xffffffffu, rm1, off, 4));
        }
        float mn0 = fmaxf(mrun[0], rm0), mn1 = fmaxf(mrun[1], rm1);
        float corr0 = __expf(mrun[0] - mn0), corr1 = __expf(mrun[1] - mn1);
        mrun[0] = mn0; mrun[1] = mn1;

        unsigned* Pw = Ps + w * PROWSW;
        float rs0 = 0.0f, rs1 = 0.0f;
        #pragma unroll
        for (int nt = 0; nt < 8; nt++) {
            float p0 = __expf(sacc[nt][0] - mn0);
            float p1 = __expf(sacc[nt][1] - mn0);
            float p2 = __expf(sacc[nt][2] - mn1);
            float p3 = __expf(sacc[nt][3] - mn1);
            rs0 += p0 + p1; rs1 += p2 + p3;
            // P row g, halfs nt*8+2t (word nt*4+t): pack half2
            Pw[(g    ) * KROWW + nt * 4 + t] = pack2(p0, p1);
            Pw[(g + 8) * KROWW + nt * 4 + t] = pack2(p2, p3);
        }
        #pragma unroll
        for (int off = 1; off < 4; off <<= 1) {
            rs0 += __shfl_xor_sync(0xffffffffu, rs0, off, 4);
            rs1 += __shfl_xor_sync(0xffffffffu, rs1, off, 4);
        }
        lrun[0] = lrun[0] * corr0 + rs0;
        lrun[1] = lrun[1] * corr1 + rs1;
        #pragma unroll
        for (int nt = 0; nt < 8; nt++) {
            oacc[nt][0] *= corr0; oacc[nt][1] *= corr0;
            oacc[nt][2] *= corr1; oacc[nt][3] *= corr1;
        }
        __syncwarp();   // Ps block is warp-private

        // O += P @ V : 4 k16 steps over 64 keys, 8 d-tiles
        #pragma unroll
        for (int ks = 0; ks < 4; ks++) {
            int kw = ks * 8;
            unsigned af[4];
            af[0] = Pw[(g    ) * KROWW + kw + t];
            af[1] = Pw[(g + 8) * KROWW + kw + t];
            af[2] = Pw[(g    ) * KROWW + kw + t + 4];
            af[3] = Pw[(g + 8) * KROWW + kw + t + 4];
            #pragma unroll
            for (int nt = 0; nt < 8; nt++) {
                unsigned bf2[2];
                bf2[0] = Vbuf[(nt * 8 + g) * KROWW + kw + t];
                bf2[1] = Vbuf[(nt * 8 + g) * KROWW + kw + t + 4];
                mma16(oacc[nt], af, bf2);
            }
        }
    }

    // Normalize and store to g_A[m][h*64+d] as half2
    const int bb = bh >> 3, h = bh & 7;
    float inv0 = 1.0f / lrun[0], inv1 = 1.0f / lrun[1];
    unsigned* gA2 = (unsigned*)g_A;
    size_t r0 = ((size_t)bb * Nn + qw + g    ) * (INNER / 2) + h * 32;
    size_t r1 = ((size_t)bb * Nn + qw + g + 8) * (INNER / 2) + h * 32;
    #pragma unroll
    for (int nt = 0; nt < 8; nt++) {
        gA2[r0 + nt * 4 + t] = pack2(oacc[nt][0] * inv0, oacc[nt][1] * inv0);
        gA2[r1 + nt * 4 + t] = pack2(oacc[nt][2] * inv1, oacc[nt][3] * inv1);
    }
}

// ---------------------------------------------------------------------------
extern "C" void kernel_launch(void* const* d_in, const int* in_sizes, int n_in,
                              void* d_out, int out_size)
{
    const float* x   = (const float*)d_in[0];
    const float* Wq  = (const float*)d_in[1];
    const float* Wkv = (const float*)d_in[2];
    const float* Wo  = (const float*)d_in[3];
    const float* bo  = (const float*)d_in[4];
    float* out = (float*)d_out;

    const int gemmSmem = GSTG * ATILEW * 4 * 2;                 // 110592 B
    const int attnSmem = (4 * KTILEW + 8 * PROWSW) * 4;         // 55296 B

    cudaFuncSetAttribute(gemm_tc, cudaFuncAttributeMaxDynamicSharedMemorySize, gemmSmem);
    cudaFuncSetAttribute(attn_tc, cudaFuncAttributeMaxDynamicSharedMemorySize, attnSmem);

    prep<<<1024, 256>>>((const float4*)x, (const float4*)Wq,
                        (const float4*)Wkv, (const float4*)Wo);
    gemm_tc<<<dim3(INNER / 128, M_TOT / 128), 256, gemmSmem>>>(nullptr, nullptr, 0);
    gemm_tc<<<dim3(2 * INNER / 128, M_TOT / 128), 256, gemmSmem>>>(nullptr, nullptr, 1);
    attn_tc<<<dim3(Nn / 128, Bb * Hh), 256, attnSmem>>>();
    gemm_tc<<<dim3(INDIM / 128, M_TOT / 128), 256, gemmSmem>>>(bo, out, 2);
}

// round 7
// speedup vs baseline: 6.4710x; 1.0580x over previous
#include <cuda_runtime.h>
#include <cuda_fp16.h>

// Problem constants
#define Hh     8
#define Dd     64
#define INDIM  512
#define Bb     4
#define Nn     2048
#define INNER  512            // H*D
#define M_TOT  (Bb*Nn)        // 8192

// Scratch (allocation-free: __device__ globals). fp16 operands, fp32 accum.
__device__ __align__(16) __half g_X  [(size_t)M_TOT*INDIM];
__device__ __align__(16) __half g_Wq [(size_t)INNER*INDIM];
__device__ __align__(16) __half g_Wkv[(size_t)2*INNER*INDIM];
__device__ __align__(16) __half g_Wo [(size_t)INDIM*INNER];
__device__ __align__(16) __half g_Q  [(size_t)Bb*Hh*Nn*Dd];  // [bh][n][d], pre-scaled 0.125*log2e
__device__ __align__(16) __half g_K  [(size_t)Bb*Hh*Nn*Dd];  // [bh][n][d]
__device__ __align__(16) __half g_V  [(size_t)Bb*Hh*Dd*Nn];  // [bh][d][n] (transposed)
__device__ __align__(16) __half g_A  [(size_t)M_TOT*INNER];  // [m][o]

// ---------------------------------------------------------------------------
// Helpers
// ---------------------------------------------------------------------------
__device__ __forceinline__ void mma16(float c[4], const unsigned a[4], const unsigned b[2]) {
    asm volatile(
        "mma.sync.aligned.m16n8k16.row.col.f32.f16.f16.f32 "
        "{%0,%1,%2,%3},{%4,%5,%6,%7},{%8,%9},{%0,%1,%2,%3};"
        : "+f"(c[0]), "+f"(c[1]), "+f"(c[2]), "+f"(c[3])
        : "r"(a[0]), "r"(a[1]), "r"(a[2]), "r"(a[3]), "r"(b[0]), "r"(b[1]));
}

__device__ __forceinline__ void ldsm4(unsigned r[4], unsigned addr) {
    asm volatile("ldmatrix.sync.aligned.m8n8.x4.shared.b16 {%0,%1,%2,%3}, [%4];"
        : "=r"(r[0]), "=r"(r[1]), "=r"(r[2]), "=r"(r[3]) : "r"(addr));
}
__device__ __forceinline__ void stsm4(unsigned addr, unsigned r0, unsigned r1,
                                      unsigned r2, unsigned r3) {
    asm volatile("stmatrix.sync.aligned.m8n8.x4.shared.b16 [%0], {%1,%2,%3,%4};"
        :: "r"(addr), "r"(r0), "r"(r1), "r"(r2), "r"(r3) : "memory");
}

__device__ __forceinline__ void cpa16(unsigned dst, const void* src) {
    asm volatile("cp.async.ca.shared.global [%0], [%1], 16;" :: "r"(dst), "l"(src));
}
#define CP_COMMIT() asm volatile("cp.async.commit_group;" ::: "memory")
#define CP_WAIT0()  asm volatile("cp.async.wait_group 0;" ::: "memory")
#define CP_WAIT1()  asm volatile("cp.async.wait_group 1;" ::: "memory")

__device__ __forceinline__ unsigned pack2(float a, float b) {
    __half2 h = __floats2half2_rn(a, b);
    return *(unsigned*)&h;
}
__device__ __forceinline__ float ex2(float x) {
    float y; asm("ex2.approx.f32 %0, %1;" : "=f"(y) : "f"(x)); return y;
}

// ---------------------------------------------------------------------------
// Prep: convert x / Wq / Wkv / Wo to fp16.
// ---------------------------------------------------------------------------
__global__ void __launch_bounds__(256) prep(
    const float4* __restrict__ x, const float4* __restrict__ wq,
    const float4* __restrict__ wkv, const float4* __restrict__ wo)
{
    const size_t nx  = (size_t)M_TOT * INDIM / 4;
    const size_t nq  = (size_t)INNER * INDIM / 4;
    const size_t nkv = (size_t)2 * INNER * INDIM / 4;
    const size_t no  = (size_t)INDIM * INNER / 4;
    const size_t total = nx + nq + nkv + no;
    for (size_t i = blockIdx.x * 256 + threadIdx.x; i < total; i += gridDim.x * 256) {
        const float4* src; __half2* dst; size_t j = i;
        if (j < nx)              { src = x;   dst = (__half2*)g_X; }
        else if ((j -= nx) < nq) { src = wq;  dst = (__half2*)g_Wq; }
        else if ((j -= nq) < nkv){ src = wkv; dst = (__half2*)g_Wkv; }
        else          { j -= nkv;  src = wo;  dst = (__half2*)g_Wo; }
        float4 v = src[j];
        dst[j * 2]     = __floats2half2_rn(v.x, v.y);
        dst[j * 2 + 1] = __floats2half2_rn(v.z, v.w);
    }
}

// ---------------------------------------------------------------------------
// Pipelined fp16 TC GEMM with ldmatrix fragment loads.
// 128x128 block tile, BK=64 halfs, 3-stage cp.async. 8 warps = 2(m) x 4(n),
// warp tile 64x32.
// ---------------------------------------------------------------------------
#define GSTG 3
#define GROWW 36                 // words per smem row (72 halfs)
#define ATILEW (128*GROWW)       // words per tile

__global__ void __launch_bounds__(256, 2) gemm_tc(
    const float* __restrict__ bias, float* __restrict__ out, int mode)
{
    extern __shared__ unsigned sm[];
    unsigned* As = sm;
    unsigned* Bs = sm + GSTG * ATILEW;

    const __half* Xp; const __half* Wp;
    if (mode == 0)      { Xp = g_X; Wp = g_Wq; }
    else if (mode == 1) { Xp = g_X; Wp = g_Wkv; }
    else                { Xp = g_A; Wp = g_Wo; }

    const int tid  = threadIdx.x;
    const int w    = tid >> 5;
    const int lane = tid & 31;
    const int g    = lane >> 2;
    const int t    = lane & 3;
    const int jj   = lane >> 3;
    const int ii   = lane & 7;
    const int wm   = (w & 1) * 64;
    const int wn   = (w >> 1) * 32;
    const int m0   = blockIdx.y * 128;
    const int n0   = blockIdx.x * 128;

    const unsigned sA = (unsigned)__cvta_generic_to_shared(As);
    const unsigned sB = (unsigned)__cvta_generic_to_shared(Bs);

    // ldmatrix per-thread word offsets within a 16-row tile
    const int taw = ((jj & 1) * 8 + ii) * GROWW + (jj >> 1) * 4;   // A frag
    const int tbw = ((jj >> 1) * 8 + ii) * GROWW + (jj & 1) * 4;   // B frag (nt pair)

    float acc[4][4][4] = {};

    auto issue = [&](int s, int k0) {
        #pragma unroll
        for (int j = 0; j < 4; j++) {
            int chunk = tid + j * 256;
            int r = chunk >> 3, c = (chunk & 7) * 8;
            cpa16(sA + ((s * 128 + r) * GROWW + c / 2) * 4,
                  Xp + (size_t)(m0 + r) * INDIM + k0 + c);
            cpa16(sB + ((s * 128 + r) * GROWW + c / 2) * 4,
                  Wp + (size_t)(n0 + r) * INDIM + k0 + c);
        }
        CP_COMMIT();
    };

    issue(0, 0);
    issue(1, 64);

    #pragma unroll 1
    for (int i = 0; i < 8; i++) {
        if (i < 6) { CP_WAIT1(); } else { CP_WAIT0(); }
        __syncthreads();
        if (i + 2 < 8) issue((i + 2) % GSTG, (i + 2) * 64);

        const unsigned sAb = sA + (i % GSTG) * ATILEW * 4;
        const unsigned sBb = sB + (i % GSTG) * ATILEW * 4;
        #pragma unroll
        for (int ks = 0; ks < 4; ks++) {
            int kw = ks * 8;
            unsigned af[4][4], bf[4][2];
            #pragma unroll
            for (int mt = 0; mt < 4; mt++)
                ldsm4(af[mt], sAb + ((wm + mt * 16) * GROWW + taw + kw) * 4);
            #pragma unroll
            for (int a = 0; a < 2; a++) {
                unsigned r[4];
                ldsm4(r, sBb + ((wn + a * 16) * GROWW + tbw + kw) * 4);
                bf[2 * a][0] = r[0]; bf[2 * a][1] = r[1];
                bf[2 * a + 1][0] = r[2]; bf[2 * a + 1][1] = r[3];
            }
            #pragma unroll
            for (int mt = 0; mt < 4; mt++)
                #pragma unroll
                for (int nt = 0; nt < 4; nt++)
                    mma16(acc[mt][nt], af[mt], bf[nt]);
        }
        __syncthreads();
    }

    // Epilogue
    #pragma unroll
    for (int mt = 0; mt < 4; mt++) {
        #pragma unroll
        for (int rr = 0; rr < 2; rr++) {
            int m = m0 + wm + mt * 16 + g + rr * 8;
            int bb = m >> 11, nn = m & 2047;
            #pragma unroll
            for (int nt = 0; nt < 4; nt++) {
                #pragma unroll
                for (int cc = 0; cc < 2; cc++) {
                    int o = n0 + wn + nt * 8 + 2 * t + cc;
                    float v = acc[mt][nt][rr * 2 + cc];
                    if (mode == 0) {
                        int h = o >> 6, d = o & 63;
                        // fold softmax scale AND log2(e) for base-2 softmax
                        g_Q[(((size_t)(bb * Hh + h) * Nn) + nn) * Dd + d] =
                            __float2half_rn(v * 0.18033688011111542f);
                    } else if (mode == 1) {
                        if (o < INNER) {
                            int h = o >> 6, d = o & 63;
                            g_K[(((size_t)(bb * Hh + h) * Nn) + nn) * Dd + d] =
                                __float2half_rn(v);
                        } else {
                            int oo = o - INNER;
                            int h = oo >> 6, d = oo & 63;
                            g_V[(((size_t)(bb * Hh + h) * Dd) + d) * Nn + nn] =
                                __float2half_rn(v);
                        }
                    } else {
                        out[(size_t)m * INNER + o] = v + bias[o];
                    }
                }
            }
        }
    }
}

// ---------------------------------------------------------------------------
// Flash attention, fp16 TC, ldmatrix/stmatrix, base-2 softmax.
// Block = 128 queries x one (b,h). 8 warps x 16 q rows. Q frags in regs.
// Smem (halfs): Ks[2][64][72], Vs[2][64][72], Ps[8][16][72].
// ---------------------------------------------------------------------------
#define KROWW 36
#define KTILEW (64*KROWW)
#define PROWSW (16*KROWW)

__global__ void __launch_bounds__(256, 2) attn_tc()
{
    extern __shared__ unsigned sm[];
    unsigned* Ks = sm;
    unsigned* Vs = sm + 2 * KTILEW;
    unsigned* Ps = sm + 4 * KTILEW;

    const int tid  = threadIdx.x;
    const int w    = tid >> 5;
    const int lane = tid & 31;
    const int g    = lane >> 2;
    const int t    = lane & 3;
    const int jj   = lane >> 3;
    const int ii   = lane & 7;
    const int bh   = blockIdx.y;
    const int qw   = blockIdx.x * 128 + w * 16;

    const unsigned sK = (unsigned)__cvta_generic_to_shared(Ks);
    const unsigned sV = (unsigned)__cvta_generic_to_shared(Vs);
    const unsigned sP = (unsigned)__cvta_generic_to_shared(Ps) + w * PROWSW * 4;

    // ldmatrix per-thread word offsets
    const int tbw = ((jj >> 1) * 8 + ii) * KROWW + (jj & 1) * 4;   // B frag (K/V, nt pair)
    const int taw = ((jj & 1) * 8 + ii) * KROWW + (jj >> 1) * 4;   // A frag (P) + P store

    // Q fragments, resident all kernel (4 k16 steps over d=64)
    unsigned qf[4][4];
    {
        const unsigned* qb = (const unsigned*)g_Q + ((size_t)bh * Nn + qw) * (Dd / 2);
        #pragma unroll
        for (int ks = 0; ks < 4; ks++) {
            int kw = ks * 8;
            qf[ks][0] = qb[(g    ) * 32 + kw + t];
            qf[ks][1] = qb[(g + 8) * 32 + kw + t];
            qf[ks][2] = qb[(g    ) * 32 + kw + t + 4];
            qf[ks][3] = qb[(g + 8) * 32 + kw + t + 4];
        }
    }

    auto issue = [&](int s, int t0) {
        #pragma unroll
        for (int j = 0; j < 2; j++) {
            int chunk = tid + j * 256;
            int r = chunk >> 3, c = (chunk & 7) * 8;
            cpa16(sK + ((s * 64 + r) * KROWW + c / 2) * 4,
                  g_K + ((size_t)bh * Nn + t0 + r) * Dd + c);
            cpa16(sV + ((s * 64 + r) * KROWW + c / 2) * 4,
                  g_V + ((size_t)bh * Dd + r) * Nn + t0 + c);
        }
        CP_COMMIT();
    };

    float oacc[8][4] = {};
    float mrun[2] = {-1e30f, -1e30f};
    float lrun[2] = {0.0f, 0.0f};

    issue(0, 0);

    #pragma unroll 1
    for (int i = 0; i < 32; i++) {
        CP_WAIT0();
        __syncthreads();
        if (i + 1 < 32) issue((i + 1) & 1, (i + 1) * 64);

        const unsigned sKb = sK + (i & 1) * KTILEW * 4;
        const unsigned sVb = sV + (i & 1) * KTILEW * 4;

        // S = Qs @ K^T : 16 x 64 per warp
        float sacc[8][4] = {};
        #pragma unroll
        for (int ks = 0; ks < 4; ks++) {
            int kw = ks * 8;
            unsigned bf[8][2];
            #pragma unroll
            for (int a = 0; a < 4; a++) {
                unsigned r[4];
                ldsm4(r, sKb + (a * 16 * KROWW + tbw + kw) * 4);
                bf[2 * a][0] = r[0]; bf[2 * a][1] = r[1];
                bf[2 * a + 1][0] = r[2]; bf[2 * a + 1][1] = r[3];
            }
            #pragma unroll
            for (int nt = 0; nt < 8; nt++)
                mma16(sacc[nt], qf[ks], bf[nt]);
        }

        // Online softmax (base 2); rows g (regs 0,1), g+8 (regs 2,3)
        float rm0 = -1e30f, rm1 = -1e30f;
        #pragma unroll
        for (int nt = 0; nt < 8; nt++) {
            rm0 = fmaxf(rm0, fmaxf(sacc[nt][0], sacc[nt][1]));
            rm1 = fmaxf(rm1, fmaxf(sacc[nt][2], sacc[nt][3]));
        }
        #pragma unroll
        for (int off = 1; off < 4; off <<= 1) {
            rm0 = fmaxf(rm0, __shfl_xor_sync(0xffffffffu, rm0, off, 4));
            rm1 = fmaxf(rm1, __shfl_xor_sync(0xffffffffu, rm1, off, 4));
        }
        float mn0 = fmaxf(mrun[0], rm0), mn1 = fmaxf(mrun[1], rm1);
        float corr0 = ex2(mrun[0] - mn0), corr1 = ex2(mrun[1] - mn1);
        mrun[0] = mn0; mrun[1] = mn1;

        float rs0 = 0.0f, rs1 = 0.0f;
        #pragma unroll
        for (int a = 0; a < 4; a++) {
            float p00 = ex2(sacc[2*a][0] - mn0),   p01 = ex2(sacc[2*a][1] - mn0);
            float p02 = ex2(sacc[2*a][2] - mn1),   p03 = ex2(sacc[2*a][3] - mn1);
            float p10 = ex2(sacc[2*a+1][0] - mn0), p11 = ex2(sacc[2*a+1][1] - mn0);
            float p12 = ex2(sacc[2*a+1][2] - mn1), p13 = ex2(sacc[2*a+1][3] - mn1);
            rs0 += p00 + p01 + p10 + p11;
            rs1 += p02 + p03 + p12 + p13;
            stsm4(sP + (taw + a * 8) * 4,
                  pack2(p00, p01), pack2(p02, p03),
                  pack2(p10, p11), pack2(p12, p13));
        }
        #pragma unroll
        for (int off = 1; off < 4; off <<= 1) {
            rs0 += __shfl_xor_sync(0xffffffffu, rs0, off, 4);
            rs1 += __shfl_xor_sync(0xffffffffu, rs1, off, 4);
        }
        lrun[0] = lrun[0] * corr0 + rs0;
        lrun[1] = lrun[1] * corr1 + rs1;
        #pragma unroll
        for (int nt = 0; nt < 8; nt++) {
            oacc[nt][0] *= corr0; oacc[nt][1] *= corr0;
            oacc[nt][2] *= corr1; oacc[nt][3] *= corr1;
        }
        __syncwarp();   // Ps block is warp-private

        // O += P @ V
        #pragma unroll
        for (int ks = 0; ks < 4; ks++) {
            int kw = ks * 8;
            unsigned af[4];
            ldsm4(af, sP + (taw + kw) * 4);
            unsigned bf[8][2];
            #pragma unroll
            for (int a = 0; a < 4; a++) {
                unsigned r[4];
                ldsm4(r, sVb + (a * 16 * KROWW + tbw + kw) * 4);
                bf[2 * a][0] = r[0]; bf[2 * a][1] = r[1];
                bf[2 * a + 1][0] = r[2]; bf[2 * a + 1][1] = r[3];
            }
            #pragma unroll
            for (int nt = 0; nt < 8; nt++)
                mma16(oacc[nt], af, bf[nt]);
        }
    }

    // Normalize and store to g_A[m][h*64+d] as half2
    const int bb = bh >> 3, h = bh & 7;
    float inv0 = 1.0f / lrun[0], inv1 = 1.0f / lrun[1];
    unsigned* gA2 = (unsigned*)g_A;
    size_t r0 = ((size_t)bb * Nn + qw + g    ) * (INNER / 2) + h * 32;
    size_t r1 = ((size_t)bb * Nn + qw + g + 8) * (INNER / 2) + h * 32;
    #pragma unroll
    for (int nt = 0; nt < 8; nt++) {
        gA2[r0 + nt * 4 + t] = pack2(oacc[nt][0] * inv0, oacc[nt][1] * inv0);
        gA2[r1 + nt * 4 + t] = pack2(oacc[nt][2] * inv1, oacc[nt][3] * inv1);
    }
}

// ---------------------------------------------------------------------------
extern "C" void kernel_launch(void* const* d_in, const int* in_sizes, int n_in,
                              void* d_out, int out_size)
{
    const float* x   = (const float*)d_in[0];
    const float* Wq  = (const float*)d_in[1];
    const float* Wkv = (const float*)d_in[2];
    const float* Wo  = (const float*)d_in[3];
    const float* bo  = (const float*)d_in[4];
    float* out = (float*)d_out;

    const int gemmSmem = GSTG * ATILEW * 4 * 2;                 // 110592 B
    const int attnSmem = (4 * KTILEW + 8 * PROWSW) * 4;         // 55296 B

    cudaFuncSetAttribute(gemm_tc, cudaFuncAttributeMaxDynamicSharedMemorySize, gemmSmem);
    cudaFuncSetAttribute(attn_tc, cudaFuncAttributeMaxDynamicSharedMemorySize, attnSmem);

    prep<<<1024, 256>>>((const float4*)x, (const float4*)Wq,
                        (const float4*)Wkv, (const float4*)Wo);
    gemm_tc<<<dim3(INNER / 128, M_TOT / 128), 256, gemmSmem>>>(nullptr, nullptr, 0);
    gemm_tc<<<dim3(2 * INNER / 128, M_TOT / 128), 256, gemmSmem>>>(nullptr, nullptr, 1);
    attn_tc<<<dim3(Nn / 128, Bb * Hh), 256, attnSmem>>>();
    gemm_tc<<<dim3(INDIM / 128, M_TOT / 128), 256, gemmSmem>>>(bo, out, 2);
}

// round 8
// speedup vs baseline: 6.5952x; 1.0192x over previous
#include <cuda_runtime.h>
#include <cuda_fp16.h>

// Problem constants
#define Hh     8
#define Dd     64
#define INDIM  512
#define Bb     4
#define Nn     2048
#define INNER  512            // H*D
#define M_TOT  (Bb*Nn)        // 8192

// Scratch (allocation-free: __device__ globals). fp16 operands, fp32 accum.
__device__ __align__(16) __half g_X  [(size_t)M_TOT*INDIM];
__device__ __align__(16) __half g_Wq [(size_t)INNER*INDIM];
__device__ __align__(16) __half g_Wkv[(size_t)2*INNER*INDIM];
__device__ __align__(16) __half g_Wo [(size_t)INDIM*INNER];
__device__ __align__(16) __half g_Q  [(size_t)Bb*Hh*Nn*Dd];  // [bh][n][d], scaled 0.125*log2e
__device__ __align__(16) __half g_K  [(size_t)Bb*Hh*Nn*Dd];  // [bh][n][d]
__device__ __align__(16) __half g_V  [(size_t)Bb*Hh*Dd*Nn];  // [bh][d][n] (transposed)
__device__ __align__(16) __half g_A  [(size_t)M_TOT*INNER];  // [m][o]

// ---------------------------------------------------------------------------
// Helpers
// ---------------------------------------------------------------------------
__device__ __forceinline__ void mma16(float c[4], const unsigned a[4], const unsigned b[2]) {
    asm volatile(
        "mma.sync.aligned.m16n8k16.row.col.f32.f16.f16.f32 "
        "{%0,%1,%2,%3},{%4,%5,%6,%7},{%8,%9},{%0,%1,%2,%3};"
        : "+f"(c[0]), "+f"(c[1]), "+f"(c[2]), "+f"(c[3])
        : "r"(a[0]), "r"(a[1]), "r"(a[2]), "r"(a[3]), "r"(b[0]), "r"(b[1]));
}

__device__ __forceinline__ void ldsm4(unsigned r[4], unsigned addr) {
    asm volatile("ldmatrix.sync.aligned.m8n8.x4.shared.b16 {%0,%1,%2,%3}, [%4];"
        : "=r"(r[0]), "=r"(r[1]), "=r"(r[2]), "=r"(r[3]) : "r"(addr));
}
__device__ __forceinline__ void stsm4(unsigned addr, unsigned r0, unsigned r1,
                                      unsigned r2, unsigned r3) {
    asm volatile("stmatrix.sync.aligned.m8n8.x4.shared.b16 [%0], {%1,%2,%3,%4};"
        :: "r"(addr), "r"(r0), "r"(r1), "r"(r2), "r"(r3) : "memory");
}

__device__ __forceinline__ void cpa16(unsigned dst, const void* src) {
    asm volatile("cp.async.ca.shared.global [%0], [%1], 16;" :: "r"(dst), "l"(src));
}
#define CP_COMMIT() asm volatile("cp.async.commit_group;" ::: "memory")
#define CP_WAIT0()  asm volatile("cp.async.wait_group 0;" ::: "memory")
#define CP_WAIT1()  asm volatile("cp.async.wait_group 1;" ::: "memory")

__device__ __forceinline__ unsigned pack2(float a, float b) {
    __half2 h = __floats2half2_rn(a, b);
    return *(unsigned*)&h;
}
__device__ __forceinline__ float ex2(float x) {
    float y; asm("ex2.approx.f32 %0, %1;" : "=f"(y) : "f"(x)); return y;
}

// ---------------------------------------------------------------------------
// Prep: convert x / Wq / Wkv / Wo to fp16.
// ---------------------------------------------------------------------------
__global__ void __launch_bounds__(256) prep(
    const float4* __restrict__ x, const float4* __restrict__ wq,
    const float4* __restrict__ wkv, const float4* __restrict__ wo)
{
    const size_t nx  = (size_t)M_TOT * INDIM / 4;
    const size_t nq  = (size_t)INNER * INDIM / 4;
    const size_t nkv = (size_t)2 * INNER * INDIM / 4;
    const size_t no  = (size_t)INDIM * INNER / 4;
    const size_t total = nx + nq + nkv + no;
    for (size_t i = blockIdx.x * 256 + threadIdx.x; i < total; i += gridDim.x * 256) {
        const float4* src; __half2* dst; size_t j = i;
        if (j < nx)              { src = x;   dst = (__half2*)g_X; }
        else if ((j -= nx) < nq) { src = wq;  dst = (__half2*)g_Wq; }
        else if ((j -= nq) < nkv){ src = wkv; dst = (__half2*)g_Wkv; }
        else          { j -= nkv;  src = wo;  dst = (__half2*)g_Wo; }
        float4 v = src[j];
        dst[j * 2]     = __floats2half2_rn(v.x, v.y);
        dst[j * 2 + 1] = __floats2half2_rn(v.z, v.w);
    }
}

// ---------------------------------------------------------------------------
// Pipelined fp16 TC GEMM, 128x256 block, BK=64, 3-stage cp.async.
// 8 warps = 2(m) x 4(n), warp tile 64x64.
// ---------------------------------------------------------------------------
#define GSTG 3
#define GROWW 36                 // words per smem row (72 halfs)
#define AT_A (128*GROWW)         // words per A tile
#define AT_B (256*GROWW)         // words per B tile

__global__ void __launch_bounds__(256, 1) gemm_tc(
    const float* __restrict__ bias, float* __restrict__ out, int mode)
{
    extern __shared__ unsigned sm[];
    unsigned* As = sm;
    unsigned* Bs = sm + GSTG * AT_A;

    const __half* Xp; const __half* Wp;
    if (mode == 0)      { Xp = g_X; Wp = g_Wq; }
    else if (mode == 1) { Xp = g_X; Wp = g_Wkv; }
    else                { Xp = g_A; Wp = g_Wo; }

    const int tid  = threadIdx.x;
    const int w    = tid >> 5;
    const int lane = tid & 31;
    const int g    = lane >> 2;
    const int t    = lane & 3;
    const int jj   = lane >> 3;
    const int ii   = lane & 7;
    const int wm   = (w & 1) * 64;
    const int wn   = (w >> 1) * 64;
    const int m0   = blockIdx.y * 128;
    const int n0   = blockIdx.x * 256;

    const unsigned sA = (unsigned)__cvta_generic_to_shared(As);
    const unsigned sB = (unsigned)__cvta_generic_to_shared(Bs);

    const int taw = ((jj & 1) * 8 + ii) * GROWW + (jj >> 1) * 4;   // A frag
    const int tbw = ((jj >> 1) * 8 + ii) * GROWW + (jj & 1) * 4;   // B frag

    float acc[4][8][4] = {};

    auto issue = [&](int s, int k0) {
        #pragma unroll
        for (int j = 0; j < 4; j++) {
            int chunk = tid + j * 256;                 // 1024 A chunks
            int r = chunk >> 3, c = (chunk & 7) * 8;
            cpa16(sA + ((s * 128 + r) * GROWW + c / 2) * 4,
                  Xp + (size_t)(m0 + r) * INDIM + k0 + c);
        }
        #pragma unroll
        for (int j = 0; j < 8; j++) {
            int chunk = tid + j * 256;                 // 2048 B chunks
            int r = chunk >> 3, c = (chunk & 7) * 8;
            cpa16(sB + ((s * 256 + r) * GROWW + c / 2) * 4,
                  Wp + (size_t)(n0 + r) * INDIM + k0 + c);
        }
        CP_COMMIT();
    };

    issue(0, 0);
    issue(1, 64);

    #pragma unroll 1
    for (int i = 0; i < 8; i++) {
        if (i < 6) { CP_WAIT1(); } else { CP_WAIT0(); }
        __syncthreads();
        if (i + 2 < 8) issue((i + 2) % GSTG, (i + 2) * 64);

        const unsigned sAb = sA + (i % GSTG) * AT_A * 4;
        const unsigned sBb = sB + (i % GSTG) * AT_B * 4;
        #pragma unroll
        for (int ks = 0; ks < 4; ks++) {
            int kw = ks * 8;
            unsigned af[4][4], bf[8][2];
            #pragma unroll
            for (int mt = 0; mt < 4; mt++)
                ldsm4(af[mt], sAb + ((wm + mt * 16) * GROWW + taw + kw) * 4);
            #pragma unroll
            for (int a = 0; a < 4; a++) {
                unsigned r[4];
                ldsm4(r, sBb + ((wn + a * 16) * GROWW + tbw + kw) * 4);
                bf[2 * a][0] = r[0]; bf[2 * a][1] = r[1];
                bf[2 * a + 1][0] = r[2]; bf[2 * a + 1][1] = r[3];
            }
            #pragma unroll
            for (int mt = 0; mt < 4; mt++)
                #pragma unroll
                for (int nt = 0; nt < 8; nt++)
                    mma16(acc[mt][nt], af[mt], bf[nt]);
        }
        __syncthreads();
    }

    // Epilogue
    #pragma unroll
    for (int mt = 0; mt < 4; mt++) {
        #pragma unroll
        for (int rr = 0; rr < 2; rr++) {
            int m = m0 + wm + mt * 16 + g + rr * 8;
            int bb = m >> 11, nn = m & 2047;
            #pragma unroll
            for (int nt = 0; nt < 8; nt++) {
                #pragma unroll
                for (int cc = 0; cc < 2; cc++) {
                    int o = n0 + wn + nt * 8 + 2 * t + cc;
                    float v = acc[mt][nt][rr * 2 + cc];
                    if (mode == 0) {
                        int h = o >> 6, d = o & 63;
                        g_Q[(((size_t)(bb * Hh + h) * Nn) + nn) * Dd + d] =
                            __float2half_rn(v * 0.18033688011111542f);
                    } else if (mode == 1) {
                        if (o < INNER) {
                            int h = o >> 6, d = o & 63;
                            g_K[(((size_t)(bb * Hh + h) * Nn) + nn) * Dd + d] =
                                __float2half_rn(v);
                        } else {
                            int oo = o - INNER;
                            int h = oo >> 6, d = oo & 63;
                            g_V[(((size_t)(bb * Hh + h) * Dd) + d) * Nn + nn] =
                                __float2half_rn(v);
                        }
                    } else {
                        out[(size_t)m * INNER + o] = v + bias[o];
                    }
                }
            }
        }
    }
}

// ---------------------------------------------------------------------------
// Flash attention, fp16 TC, ldmatrix/stmatrix, base-2 softmax.
// Block = 256 queries x one (b,h). 8 warps, warp tile 32q x 64 keys.
// Smem (halfs): Ks[2][64][72], Vs[2][64][72], Ps[8][32][72].
// ---------------------------------------------------------------------------
#define KROWW 36
#define KTILEW (64*KROWW)
#define PROWSW (32*KROWW)       // per-warp P block (32 rows)

__global__ void __launch_bounds__(256, 1) attn_tc()
{
    extern __shared__ unsigned sm[];
    unsigned* Ks = sm;
    unsigned* Vs = sm + 2 * KTILEW;
    unsigned* Ps = sm + 4 * KTILEW;

    const int tid  = threadIdx.x;
    const int w    = tid >> 5;
    const int lane = tid & 31;
    const int g    = lane >> 2;
    const int t    = lane & 3;
    const int jj   = lane >> 3;
    const int ii   = lane & 7;
    const int bh   = blockIdx.y;
    const int qw   = blockIdx.x * 256 + w * 32;

    const unsigned sK = (unsigned)__cvta_generic_to_shared(Ks);
    const unsigned sV = (unsigned)__cvta_generic_to_shared(Vs);
    const unsigned sP = (unsigned)__cvta_generic_to_shared(Ps) + w * PROWSW * 4;

    const int tbw = ((jj >> 1) * 8 + ii) * KROWW + (jj & 1) * 4;   // B frag (K/V)
    const int taw = ((jj & 1) * 8 + ii) * KROWW + (jj >> 1) * 4;   // A frag (P) + P store

    // Q fragments: 2 m-tiles x 4 k16 steps, resident all kernel
    unsigned qf[2][4][4];
    {
        const unsigned* qb = (const unsigned*)g_Q + ((size_t)bh * Nn + qw) * (Dd / 2);
        #pragma unroll
        for (int mt = 0; mt < 2; mt++)
            #pragma unroll
            for (int ks = 0; ks < 4; ks++) {
                int kw = ks * 8;
                qf[mt][ks][0] = qb[(mt * 16 + g    ) * 32 + kw + t];
                qf[mt][ks][1] = qb[(mt * 16 + g + 8) * 32 + kw + t];
                qf[mt][ks][2] = qb[(mt * 16 + g    ) * 32 + kw + t + 4];
                qf[mt][ks][3] = qb[(mt * 16 + g + 8) * 32 + kw + t + 4];
            }
    }

    auto issue = [&](int s, int t0) {
        #pragma unroll
        for (int j = 0; j < 2; j++) {
            int chunk = tid + j * 256;
            int r = chunk >> 3, c = (chunk & 7) * 8;
            cpa16(sK + ((s * 64 + r) * KROWW + c / 2) * 4,
                  g_K + ((size_t)bh * Nn + t0 + r) * Dd + c);
            cpa16(sV + ((s * 64 + r) * KROWW + c / 2) * 4,
                  g_V + ((size_t)bh * Dd + r) * Nn + t0 + c);
        }
        CP_COMMIT();
    };

    float oacc[2][8][4] = {};
    float mrun[2][2] = {{-1e30f, -1e30f}, {-1e30f, -1e30f}};
    float lrun[2][2] = {{0.0f, 0.0f}, {0.0f, 0.0f}};

    issue(0, 0);

    #pragma unroll 1
    for (int i = 0; i < 32; i++) {
        CP_WAIT0();
        __syncthreads();
        if (i + 1 < 32) issue((i + 1) & 1, (i + 1) * 64);

        const unsigned sKb = sK + (i & 1) * KTILEW * 4;
        const unsigned sVb = sV + (i & 1) * KTILEW * 4;

        // S = Qs @ K^T : 32 x 64 per warp
        float sacc[2][8][4] = {};
        #pragma unroll
        for (int ks = 0; ks < 4; ks++) {
            int kw = ks * 8;
            unsigned bf[8][2];
            #pragma unroll
            for (int a = 0; a < 4; a++) {
                unsigned r[4];
                ldsm4(r, sKb + (a * 16 * KROWW + tbw + kw) * 4);
                bf[2 * a][0] = r[0]; bf[2 * a][1] = r[1];
                bf[2 * a + 1][0] = r[2]; bf[2 * a + 1][1] = r[3];
            }
            #pragma unroll
            for (int mt = 0; mt < 2; mt++)
                #pragma unroll
                for (int nt = 0; nt < 8; nt++)
                    mma16(sacc[mt][nt], qf[mt][ks], bf[nt]);
        }

        // Online softmax (base 2), per m-tile
        #pragma unroll
        for (int mt = 0; mt < 2; mt++) {
            float rm0 = -1e30f, rm1 = -1e30f;
            #pragma unroll
            for (int nt = 0; nt < 8; nt++) {
                rm0 = fmaxf(rm0, fmaxf(sacc[mt][nt][0], sacc[mt][nt][1]));
                rm1 = fmaxf(rm1, fmaxf(sacc[mt][nt][2], sacc[mt][nt][3]));
            }
            #pragma unroll
            for (int off = 1; off < 4; off <<= 1) {
                rm0 = fmaxf(rm0, __shfl_xor_sync(0xffffffffu, rm0, off, 4));
                rm1 = fmaxf(rm1, __shfl_xor_sync(0xffffffffu, rm1, off, 4));
            }
            float mn0 = fmaxf(mrun[mt][0], rm0), mn1 = fmaxf(mrun[mt][1], rm1);
            float corr0 = ex2(mrun[mt][0] - mn0), corr1 = ex2(mrun[mt][1] - mn1);
            mrun[mt][0] = mn0; mrun[mt][1] = mn1;

            float rs0 = 0.0f, rs1 = 0.0f;
            #pragma unroll
            for (int a = 0; a < 4; a++) {
                float p00 = ex2(sacc[mt][2*a][0] - mn0),   p01 = ex2(sacc[mt][2*a][1] - mn0);
                float p02 = ex2(sacc[mt][2*a][2] - mn1),   p03 = ex2(sacc[mt][2*a][3] - mn1);
                float p10 = ex2(sacc[mt][2*a+1][0] - mn0), p11 = ex2(sacc[mt][2*a+1][1] - mn0);
                float p12 = ex2(sacc[mt][2*a+1][2] - mn1), p13 = ex2(sacc[mt][2*a+1][3] - mn1);
                rs0 += p00 + p01 + p10 + p11;
                rs1 += p02 + p03 + p12 + p13;
                stsm4(sP + (mt * 16 * KROWW + taw + a * 8) * 4,
                      pack2(p00, p01), pack2(p02, p03),
                      pack2(p10, p11), pack2(p12, p13));
            }
            #pragma unroll
            for (int off = 1; off < 4; off <<= 1) {
                rs0 += __shfl_xor_sync(0xffffffffu, rs0, off, 4);
                rs1 += __shfl_xor_sync(0xffffffffu, rs1, off, 4);
            }
            lrun[mt][0] = lrun[mt][0] * corr0 + rs0;
            lrun[mt][1] = lrun[mt][1] * corr1 + rs1;
            #pragma unroll
            for (int nt = 0; nt < 8; nt++) {
                oacc[mt][nt][0] *= corr0; oacc[mt][nt][1] *= corr0;
                oacc[mt][nt][2] *= corr1; oacc[mt][nt][3] *= corr1;
            }
        }
        __syncwarp();   // Ps block is warp-private

        // O += P @ V
        #pragma unroll
        for (int ks = 0; ks < 4; ks++) {
            int kw = ks * 8;
            unsigned af[2][4];
            #pragma unroll
            for (int mt = 0; mt < 2; mt++)
                ldsm4(af[mt], sP + (mt * 16 * KROWW + taw + kw) * 4);
            unsigned bf[8][2];
            #pragma unroll
            for (int a = 0; a < 4; a++) {
                unsigned r[4];
                ldsm4(r, sVb + (a * 16 * KROWW + tbw + kw) * 4);
                bf[2 * a][0] = r[0]; bf[2 * a][1] = r[1];
                bf[2 * a + 1][0] = r[2]; bf[2 * a + 1][1] = r[3];
            }
            #pragma unroll
            for (int mt = 0; mt < 2; mt++)
                #pragma unroll
                for (int nt = 0; nt < 8; nt++)
                    mma16(oacc[mt][nt], af[mt], bf[nt]);
        }
    }

    // Normalize and store to g_A[m][h*64+d] as half2
    const int bb = bh >> 3, h = bh & 7;
    unsigned* gA2 = (unsigned*)g_A;
    #pragma unroll
    for (int mt = 0; mt < 2; mt++) {
        float inv0 = 1.0f / lrun[mt][0], inv1 = 1.0f / lrun[mt][1];
        size_t r0 = ((size_t)bb * Nn + qw + mt * 16 + g    ) * (INNER / 2) + h * 32;
        size_t r1 = ((size_t)bb * Nn + qw + mt * 16 + g + 8) * (INNER / 2) + h * 32;
        #pragma unroll
        for (int nt = 0; nt < 8; nt++) {
            gA2[r0 + nt * 4 + t] = pack2(oacc[mt][nt][0] * inv0, oacc[mt][nt][1] * inv0);
            gA2[r1 + nt * 4 + t] = pack2(oacc[mt][nt][2] * inv1, oacc[mt][nt][3] * inv1);
        }
    }
}

// ---------------------------------------------------------------------------
extern "C" void kernel_launch(void* const* d_in, const int* in_sizes, int n_in,
                              void* d_out, int out_size)
{
    const float* x   = (const float*)d_in[0];
    const float* Wq  = (const float*)d_in[1];
    const float* Wkv = (const float*)d_in[2];
    const float* Wo  = (const float*)d_in[3];
    const float* bo  = (const float*)d_in[4];
    float* out = (float*)d_out;

    const int gemmSmem = GSTG * (AT_A + AT_B) * 4;              // 165888 B
    const int attnSmem = (4 * KTILEW + 8 * PROWSW) * 4;         // 73728 B

    cudaFuncSetAttribute(gemm_tc, cudaFuncAttributeMaxDynamicSharedMemorySize, gemmSmem);
    cudaFuncSetAttribute(attn_tc, cudaFuncAttributeMaxDynamicSharedMemorySize, attnSmem);

    prep<<<1024, 256>>>((const float4*)x, (const float4*)Wq,
                        (const float4*)Wkv, (const float4*)Wo);
    gemm_tc<<<dim3(INNER / 256, M_TOT / 128), 256, gemmSmem>>>(nullptr, nullptr, 0);
    gemm_tc<<<dim3(2 * INNER / 256, M_TOT / 128), 256, gemmSmem>>>(nullptr, nullptr, 1);
    attn_tc<<<dim3(Nn / 256, Bb * Hh), 256, attnSmem>>>();
    gemm_tc<<<dim3(INDIM / 256, M_TOT / 128), 256, gemmSmem>>>(bo, out, 2);
}

// round 10
// speedup vs baseline: 6.8241x; 1.0347x over previous
#include <cuda_runtime.h>
#include <cuda_fp16.h>
#include <cstdint>

// Problem constants
#define Hh     8
#define Dd     64
#define INDIM  512
#define Bb     4
#define Nn     2048
#define INNER  512            // H*D
#define M_TOT  (Bb*Nn)        // 8192

// Scratch (allocation-free: __device__ globals). fp16 operands, fp32 accum.
__device__ __align__(16) __half g_X   [(size_t)M_TOT*INDIM];
__device__ __align__(16) __half g_Wqkv[(size_t)3*INNER*INDIM];  // Wq ‖ Wkv
__device__ __align__(16) __half g_Wo  [(size_t)INDIM*INNER];
__device__ __align__(16) __half g_Q   [(size_t)Bb*Hh*Nn*Dd];  // [bh][n][d], scaled 0.125*log2e
__device__ __align__(16) __half g_K   [(size_t)Bb*Hh*Nn*Dd];  // [bh][n][d]
__device__ __align__(16) __half g_V   [(size_t)Bb*Hh*Dd*Nn];  // [bh][d][n] (transposed)
__device__ __align__(16) __half g_A   [(size_t)M_TOT*INNER];  // [m][o]

// ---------------------------------------------------------------------------
// Helpers
// ---------------------------------------------------------------------------
__device__ __forceinline__ void mma16(float c[4], const unsigned a[4], const unsigned b[2]) {
    asm volatile(
        "mma.sync.aligned.m16n8k16.row.col.f32.f16.f16.f32 "
        "{%0,%1,%2,%3},{%4,%5,%6,%7},{%8,%9},{%0,%1,%2,%3};"
        : "+f"(c[0]), "+f"(c[1]), "+f"(c[2]), "+f"(c[3])
        : "r"(a[0]), "r"(a[1]), "r"(a[2]), "r"(a[3]), "r"(b[0]), "r"(b[1]));
}
__device__ __forceinline__ void ldsm4(unsigned r[4], unsigned addr) {
    asm volatile("ldmatrix.sync.aligned.m8n8.x4.shared.b16 {%0,%1,%2,%3}, [%4];"
        : "=r"(r[0]), "=r"(r[1]), "=r"(r[2]), "=r"(r[3]) : "r"(addr));
}
__device__ __forceinline__ void stsm4(unsigned addr, unsigned r0, unsigned r1,
                                      unsigned r2, unsigned r3) {
    asm volatile("stmatrix.sync.aligned.m8n8.x4.shared.b16 [%0], {%1,%2,%3,%4};"
        :: "r"(addr), "r"(r0), "r"(r1), "r"(r2), "r"(r3) : "memory");
}
__device__ __forceinline__ void cpa16(unsigned dst, const void* src) {
    asm volatile("cp.async.ca.shared.global [%0], [%1], 16;" :: "r"(dst), "l"(src));
}
#define CP_COMMIT() asm volatile("cp.async.commit_group;" ::: "memory")
#define CP_WAIT0()  asm volatile("cp.async.wait_group 0;" ::: "memory")
#define CP_WAIT1()  asm volatile("cp.async.wait_group 1;" ::: "memory")

__device__ __forceinline__ unsigned pack2(float a, float b) {
    __half2 h = __floats2half2_rn(a, b);
    return *(unsigned*)&h;
}
__device__ __forceinline__ float ex2(float x) {
    float y; asm("ex2.approx.f32 %0, %1;" : "=f"(y) : "f"(x)); return y;
}
__device__ __forceinline__ unsigned ex2h2(unsigned x) {
    unsigned y; asm("ex2.approx.f16x2 %0, %1;" : "=r"(y) : "r"(x)); return y;
}

// ---------------------------------------------------------------------------
// Prep: convert x / Wq / Wkv / Wo to fp16 (Wq,Wkv packed contiguously).
// ---------------------------------------------------------------------------
__global__ void __launch_bounds__(256) prep(
    const float4* __restrict__ x, const float4* __restrict__ wq,
    const float4* __restrict__ wkv, const float4* __restrict__ wo)
{
    const size_t nx  = (size_t)M_TOT * INDIM / 4;
    const size_t nq  = (size_t)INNER * INDIM / 4;
    const size_t nkv = (size_t)2 * INNER * INDIM / 4;
    const size_t no  = (size_t)INDIM * INNER / 4;
    const size_t total = nx + nq + nkv + no;
    for (size_t i = blockIdx.x * 256 + threadIdx.x; i < total; i += gridDim.x * 256) {
        const float4* src; __half2* dst; size_t j = i;
        if (j < nx)              { src = x;   dst = (__half2*)g_X; }
        else if ((j -= nx) < nq) { src = wq;  dst = (__half2*)g_Wqkv; }
        else if ((j -= nq) < nkv){ src = wkv; dst = (__half2*)(g_Wqkv + (size_t)INNER*INDIM); }
        else          { j -= nkv;  src = wo;  dst = (__half2*)g_Wo; }
        float4 v = src[j];
        dst[j * 2]     = __floats2half2_rn(v.x, v.y);
        dst[j * 2 + 1] = __floats2half2_rn(v.z, v.w);
    }
}

// ---------------------------------------------------------------------------
// Pipelined fp16 TC GEMM, 128x256 block, BK=64, 3-stage cp.async.
// 8 warps = 2(m) x 4(n), warp tile 64x64.
// mode 0: X @ Wqkv^T (N=1536) -> g_Q (scaled) / g_K / g_V(transposed)
// mode 2: g_A @ Wo^T (N=512)  -> out + bias
// ---------------------------------------------------------------------------
#define GSTG 3
#define GROWW 36                 // words per smem row (72 halfs)
#define AT_A (128*GROWW)
#define AT_B (256*GROWW)

__global__ void __launch_bounds__(256, 1) gemm_tc(
    const float* __restrict__ bias, float* __restrict__ out, int mode)
{
    extern __shared__ unsigned sm[];
    unsigned* As = sm;
    unsigned* Bs = sm + GSTG * AT_A;

    const __half* Xp; const __half* Wp;
    if (mode == 0) { Xp = g_X; Wp = g_Wqkv; }
    else           { Xp = g_A; Wp = g_Wo; }

    const int tid  = threadIdx.x;
    const int w    = tid >> 5;
    const int lane = tid & 31;
    const int g    = lane >> 2;
    const int t    = lane & 3;
    const int jj   = lane >> 3;
    const int ii   = lane & 7;
    const int wm   = (w & 1) * 64;
    const int wn   = (w >> 1) * 64;
    const int m0   = blockIdx.y * 128;
    const int n0   = blockIdx.x * 256;

    const unsigned sA = (unsigned)__cvta_generic_to_shared(As);
    const unsigned sB = (unsigned)__cvta_generic_to_shared(Bs);

    const int taw = ((jj & 1) * 8 + ii) * GROWW + (jj >> 1) * 4;
    const int tbw = ((jj >> 1) * 8 + ii) * GROWW + (jj & 1) * 4;

    float acc[4][8][4] = {};

    auto issue = [&](int s, int k0) {
        #pragma unroll
        for (int j = 0; j < 4; j++) {
            int chunk = tid + j * 256;
            int r = chunk >> 3, c = (chunk & 7) * 8;
            cpa16(sA + ((s * 128 + r) * GROWW + c / 2) * 4,
                  Xp + (size_t)(m0 + r) * INDIM + k0 + c);
        }
        #pragma unroll
        for (int j = 0; j < 8; j++) {
            int chunk = tid + j * 256;
            int r = chunk >> 3, c = (chunk & 7) * 8;
            cpa16(sB + ((s * 256 + r) * GROWW + c / 2) * 4,
                  Wp + (size_t)(n0 + r) * INDIM + k0 + c);
        }
        CP_COMMIT();
    };

    issue(0, 0);
    issue(1, 64);

    #pragma unroll 1
    for (int i = 0; i < 8; i++) {
        if (i < 6) { CP_WAIT1(); } else { CP_WAIT0(); }
        __syncthreads();
        if (i + 2 < 8) issue((i + 2) % GSTG, (i + 2) * 64);

        const unsigned sAb = sA + (i % GSTG) * AT_A * 4;
        const unsigned sBb = sB + (i % GSTG) * AT_B * 4;
        #pragma unroll
        for (int ks = 0; ks < 4; ks++) {
            int kw = ks * 8;
            unsigned af[4][4], bf[8][2];
            #pragma unroll
            for (int mt = 0; mt < 4; mt++)
                ldsm4(af[mt], sAb + ((wm + mt * 16) * GROWW + taw + kw) * 4);
            #pragma unroll
            for (int a = 0; a < 4; a++) {
                unsigned r[4];
                ldsm4(r, sBb + ((wn + a * 16) * GROWW + tbw + kw) * 4);
                bf[2 * a][0] = r[0]; bf[2 * a][1] = r[1];
                bf[2 * a + 1][0] = r[2]; bf[2 * a + 1][1] = r[3];
            }
            #pragma unroll
            for (int mt = 0; mt < 4; mt++)
                #pragma unroll
                for (int nt = 0; nt < 8; nt++)
                    mma16(acc[mt][nt], af[mt], bf[nt]);
        }
        __syncthreads();
    }

    // Epilogue
    #pragma unroll
    for (int mt = 0; mt < 4; mt++) {
        #pragma unroll
        for (int rr = 0; rr < 2; rr++) {
            int m = m0 + wm + mt * 16 + g + rr * 8;
            int bb = m >> 11, nn = m & 2047;
            #pragma unroll
            for (int nt = 0; nt < 8; nt++) {
                #pragma unroll
                for (int cc = 0; cc < 2; cc++) {
                    int o = n0 + wn + nt * 8 + 2 * t + cc;
                    float v = acc[mt][nt][rr * 2 + cc];
                    if (mode == 0) {
                        if (o < INNER) {
                            int h = o >> 6, d = o & 63;
                            g_Q[(((size_t)(bb * Hh + h) * Nn) + nn) * Dd + d] =
                                __float2half_rn(v * 0.18033688011111542f);
                        } else if (o < 2 * INNER) {
                            int oo = o - INNER, h = oo >> 6, d = oo & 63;
                            g_K[(((size_t)(bb * Hh + h) * Nn) + nn) * Dd + d] =
                                __float2half_rn(v);
                        } else {
                            int oo = o - 2 * INNER, h = oo >> 6, d = oo & 63;
                            g_V[(((size_t)(bb * Hh + h) * Dd) + d) * Nn + nn] =
                                __float2half_rn(v);
                        }
                    } else {
                        out[(size_t)m * INNER + o] = v + bias[o];
                    }
                }
            }
        }
    }
}

// ---------------------------------------------------------------------------
// Flash attention, fp16 TC, ldmatrix/stmatrix, base-2 softmax with
// f16x2 ex2 and ones-column row sums. Block = 256 q x one (b,h);
// 8 warps, warp tile 32q x 64 keys.
// ---------------------------------------------------------------------------
#define KROWW 36
#define KTILEW (64*KROWW)
#define PROWSW (32*KROWW)
#define ONES2 0x3C003C00u

__global__ void __launch_bounds__(256, 1) attn_tc()
{
    extern __shared__ unsigned sm[];
    unsigned* Ks = sm;
    unsigned* Vs = sm + 2 * KTILEW;
    unsigned* Ps = sm + 4 * KTILEW;

    const int tid  = threadIdx.x;
    const int w    = tid >> 5;
    const int lane = tid & 31;
    const int g    = lane >> 2;
    const int t    = lane & 3;
    const int jj   = lane >> 3;
    const int ii   = lane & 7;
    const int bh   = blockIdx.y;
    const int qw   = blockIdx.x * 256 + w * 32;

    const unsigned sK = (unsigned)__cvta_generic_to_shared(Ks);
    const unsigned sV = (unsigned)__cvta_generic_to_shared(Vs);
    const unsigned sP = (unsigned)__cvta_generic_to_shared(Ps) + w * PROWSW * 4;

    const int tbw = ((jj >> 1) * 8 + ii) * KROWW + (jj & 1) * 4;
    const int taw = ((jj & 1) * 8 + ii) * KROWW + (jj >> 1) * 4;

    unsigned qf[2][4][4];
    {
        const unsigned* qb = (const unsigned*)g_Q + ((size_t)bh * Nn + qw) * (Dd / 2);
        #pragma unroll
        for (int mt = 0; mt < 2; mt++)
            #pragma unroll
            for (int ks = 0; ks < 4; ks++) {
                int kw = ks * 8;
                qf[mt][ks][0] = qb[(mt * 16 + g    ) * 32 + kw + t];
                qf[mt][ks][1] = qb[(mt * 16 + g + 8) * 32 + kw + t];
                qf[mt][ks][2] = qb[(mt * 16 + g    ) * 32 + kw + t + 4];
                qf[mt][ks][3] = qb[(mt * 16 + g + 8) * 32 + kw + t + 4];
            }
    }

    auto issue = [&](int s, int t0) {
        #pragma unroll
        for (int j = 0; j < 2; j++) {
            int chunk = tid + j * 256;
            int r = chunk >> 3, c = (chunk & 7) * 8;
            cpa16(sK + ((s * 64 + r) * KROWW + c / 2) * 4,
                  g_K + ((size_t)bh * Nn + t0 + r) * Dd + c);
            cpa16(sV + ((s * 64 + r) * KROWW + c / 2) * 4,
                  g_V + ((size_t)bh * Dd + r) * Nn + t0 + c);
        }
        CP_COMMIT();
    };

    float oacc[2][9][4] = {};   // nt=8 column accumulates row sums (P @ ones)
    float mrun[2][2] = {{-1e30f, -1e30f}, {-1e30f, -1e30f}};

    issue(0, 0);

    #pragma unroll 1
    for (int i = 0; i < 32; i++) {
        CP_WAIT0();
        __syncthreads();
        if (i + 1 < 32) issue((i + 1) & 1, (i + 1) * 64);

        const unsigned sKb = sK + (i & 1) * KTILEW * 4;
        const unsigned sVb = sV + (i & 1) * KTILEW * 4;

        // S = Qs @ K^T : 32 x 64 per warp
        float sacc[2][8][4] = {};
        #pragma unroll
        for (int ks = 0; ks < 4; ks++) {
            int kw = ks * 8;
            unsigned bf[8][2];
            #pragma unroll
            for (int a = 0; a < 4; a++) {
                unsigned r[4];
                ldsm4(r, sKb + (a * 16 * KROWW + tbw + kw) * 4);
                bf[2 * a][0] = r[0]; bf[2 * a][1] = r[1];
                bf[2 * a + 1][0] = r[2]; bf[2 * a + 1][1] = r[3];
            }
            #pragma unroll
            for (int mt = 0; mt < 2; mt++)
                #pragma unroll
                for (int nt = 0; nt < 8; nt++)
                    mma16(sacc[mt][nt], qf[mt][ks], bf[nt]);
        }

        // Online softmax (base 2), f16x2 exp; P row sums via ones-column mma
        #pragma unroll
        for (int mt = 0; mt < 2; mt++) {
            float rm0 = -1e30f, rm1 = -1e30f;
            #pragma unroll
            for (int nt = 0; nt < 8; nt++) {
                rm0 = fmaxf(rm0, fmaxf(sacc[mt][nt][0], sacc[mt][nt][1]));
                rm1 = fmaxf(rm1, fmaxf(sacc[mt][nt][2], sacc[mt][nt][3]));
            }
            #pragma unroll
            for (int off = 1; off < 4; off <<= 1) {
                rm0 = fmaxf(rm0, __shfl_xor_sync(0xffffffffu, rm0, off, 4));
                rm1 = fmaxf(rm1, __shfl_xor_sync(0xffffffffu, rm1, off, 4));
            }
            float mn0 = fmaxf(mrun[mt][0], rm0), mn1 = fmaxf(mrun[mt][1], rm1);
            float corr0 = ex2(mrun[mt][0] - mn0), corr1 = ex2(mrun[mt][1] - mn1);
            mrun[mt][0] = mn0; mrun[mt][1] = mn1;

            #pragma unroll
            for (int a = 0; a < 4; a++) {
                unsigned h00 = ex2h2(pack2(sacc[mt][2*a  ][0] - mn0, sacc[mt][2*a  ][1] - mn0));
                unsigned h01 = ex2h2(pack2(sacc[mt][2*a  ][2] - mn1, sacc[mt][2*a  ][3] - mn1));
                unsigned h10 = ex2h2(pack2(sacc[mt][2*a+1][0] - mn0, sacc[mt][2*a+1][1] - mn0));
                unsigned h11 = ex2h2(pack2(sacc[mt][2*a+1][2] - mn1, sacc[mt][2*a+1][3] - mn1));
                stsm4(sP + (mt * 16 * KROWW + taw + a * 8) * 4, h00, h01, h10, h11);
            }
            #pragma unroll
            for (int nt = 0; nt < 9; nt++) {
                oacc[mt][nt][0] *= corr0; oacc[mt][nt][1] *= corr0;
                oacc[mt][nt][2] *= corr1; oacc[mt][nt][3] *= corr1;
            }
        }
        __syncwarp();   // Ps block is warp-private

        // O += P @ V  (plus ones-column for row sums)
        #pragma unroll
        for (int ks = 0; ks < 4; ks++) {
            int kw = ks * 8;
            unsigned af[2][4];
            #pragma unroll
            for (int mt = 0; mt < 2; mt++)
                ldsm4(af[mt], sP + (mt * 16 * KROWW + taw + kw) * 4);
            unsigned bf[8][2];
            #pragma unroll
            for (int a = 0; a < 4; a++) {
                unsigned r[4];
                ldsm4(r, sVb + (a * 16 * KROWW + tbw + kw) * 4);
                bf[2 * a][0] = r[0]; bf[2 * a][1] = r[1];
                bf[2 * a + 1][0] = r[2]; bf[2 * a + 1][1] = r[3];
            }
            unsigned bones[2] = {ONES2, ONES2};
            #pragma unroll
            for (int mt = 0; mt < 2; mt++) {
                #pragma unroll
                for (int nt = 0; nt < 8; nt++)
                    mma16(oacc[mt][nt], af[mt], bf[nt]);
                mma16(oacc[mt][8], af[mt], bones);
            }
        }
    }

    // Normalize by the ones-column sums and store to g_A[m][h*64+d] as half2
    const int bb = bh >> 3, h = bh & 7;
    unsigned* gA2 = (unsigned*)g_A;
    #pragma unroll
    for (int mt = 0; mt < 2; mt++) {
        float inv0 = 1.0f / oacc[mt][8][0];
        float inv1 = 1.0f / oacc[mt][8][2];
        size_t r0 = ((size_t)bb * Nn + qw + mt * 16 + g    ) * (INNER / 2) + h * 32;
        size_t r1 = ((size_t)bb * Nn + qw + mt * 16 + g + 8) * (INNER / 2) + h * 32;
        #pragma unroll
        for (int nt = 0; nt < 8; nt++) {
            gA2[r0 + nt * 4 + t] = pack2(oacc[mt][nt][0] * inv0, oacc[mt][nt][1] * inv0);
            gA2[r1 + nt * 4 + t] = pack2(oacc[mt][nt][2] * inv1, oacc[mt][nt][3] * inv1);
        }
    }
}

// ---------------------------------------------------------------------------
extern "C" void kernel_launch(void* const* d_in, const int* in_sizes, int n_in,
                              void* d_out, int out_size)
{
    const float* x   = (const float*)d_in[0];
    const float* Wq  = (const float*)d_in[1];
    const float* Wkv = (const float*)d_in[2];
    const float* Wo  = (const float*)d_in[3];
    const float* bo  = (const float*)d_in[4];
    float* out = (float*)d_out;

    const int gemmSmem = GSTG * (AT_A + AT_B) * 4;              // 165888 B
    const int attnSmem = (4 * KTILEW + 8 * PROWSW) * 4;         // 73728 B

    cudaFuncSetAttribute(gemm_tc, cudaFuncAttributeMaxDynamicSharedMemorySize, gemmSmem);
    cudaFuncSetAttribute(attn_tc, cudaFuncAttributeMaxDynamicSharedMemorySize, attnSmem);

    prep<<<1024, 256>>>((const float4*)x, (const float4*)Wq,
                        (const float4*)Wkv, (const float4*)Wo);
    // Fused Q+K+V projection: N = 1536
    gemm_tc<<<dim3(3 * INNER / 256, M_TOT / 128), 256, gemmSmem>>>(nullptr, nullptr, 0);
    attn_tc<<<dim3(Nn / 256, Bb * Hh), 256, attnSmem>>>();
    // Output projection + bias: N = 512
    gemm_tc<<<dim3(INDIM / 256, M_TOT / 128), 256, gemmSmem>>>(bo, out, 2);
}